// round 3
// baseline (speedup 1.0000x reference)
#include <cuda_runtime.h>
#include <math.h>

#define Cdim   192
#define NHEAD  8
#define HDIM   24
#define HWPIX  12544          // 112*112
#define LTOK   784            // 7*112
#define KDIM   192
#define NPIX   12544
#define M_QKV  576
#define M_PROJ 192
#define SCALE_F 0.20412414523193154f  // 24^-0.5

// ---------------- scratch (device globals; no allocation) ----------------
__device__ float g_qkv_h[M_QKV * HWPIX];
__device__ float g_qkv_v[M_QKV * HWPIX];
__device__ float g_att_h[Cdim * HWPIX];
__device__ float g_att_v[Cdim * HWPIX];
__device__ float g_lep_h[Cdim * HWPIX];
__device__ float g_lep_v[Cdim * HWPIX];

// ---------------- f32x2 helpers ----------------
__device__ __forceinline__ unsigned long long f2pack(float a, float b) {
    unsigned long long r;
    asm("mov.b64 %0, {%1,%2};" : "=l"(r) : "f"(a), "f"(b));
    return r;
}
__device__ __forceinline__ unsigned long long f2fma(unsigned long long a,
                                                    unsigned long long b,
                                                    unsigned long long c) {
    unsigned long long r;
    asm("fma.rn.f32x2 %0, %1, %2, %3;" : "=l"(r) : "l"(a), "l"(b), "l"(c));
    return r;
}
__device__ __forceinline__ float2 f2unpack(unsigned long long a) {
    float2 f;
    asm("mov.b64 {%0,%1}, %2;" : "=f"(f.x), "=f"(f.y) : "l"(a));
    return f;
}

union U6 {
    float4 v4[6];
    unsigned long long u[12];
    float f[24];
};
union U2 {
    float4 v4;
    unsigned long long u[2];
};

// ---------------- GEMM: C[M,N] = A[M,K] * B[K,N] + bias (f32x2, no pack MOVs) --------
// 64M x 128N tiles, 256 threads, per-thread 4x8 (4x4 f32x2 accumulators).
// As stored DUPLICATED (a,a) so LDS.128 yields ready f32x2 broadcast operands.
template<bool PROJ>
__global__ __launch_bounds__(256) void gemm_t(
    const float* __restrict__ A, const float* __restrict__ B1,
    const float* __restrict__ B2, const float* __restrict__ bias,
    float* __restrict__ C)
{
    __shared__ float Asd[16][132];   // duplicated: [k][2m],[k][2m+1] = A[m][k]
    __shared__ float Bs[16][128];
    const int bm = blockIdx.y * 64, bn = blockIdx.x * 128;
    const int tid = threadIdx.x;
    const int tx = tid & 15, ty = tid >> 4;
    const int mA = tid >> 2, kA = (tid & 3) * 4;
    const int rB = tid >> 5, cB = (tid & 31) * 4;

    unsigned long long acc[4][4];
    #pragma unroll
    for (int i = 0; i < 4; i++)
        #pragma unroll
        for (int j = 0; j < 4; j++) acc[i][j] = 0ull;

    float4 ra, rb0, rb1;
    ra = *(const float4*)&A[(bm + mA) * KDIM + kA];
    if (PROJ) {
        float4 a0 = *(const float4*)&B1[rB * NPIX + bn + cB];
        float4 c0 = *(const float4*)&B2[rB * NPIX + bn + cB];
        rb0 = make_float4(0.5f*(a0.x+c0.x), 0.5f*(a0.y+c0.y), 0.5f*(a0.z+c0.z), 0.5f*(a0.w+c0.w));
        float4 a1 = *(const float4*)&B1[(8 + rB) * NPIX + bn + cB];
        float4 c1 = *(const float4*)&B2[(8 + rB) * NPIX + bn + cB];
        rb1 = make_float4(0.5f*(a1.x+c1.x), 0.5f*(a1.y+c1.y), 0.5f*(a1.z+c1.z), 0.5f*(a1.w+c1.w));
    } else {
        rb0 = *(const float4*)&B1[rB * NPIX + bn + cB];
        rb1 = *(const float4*)&B1[(8 + rB) * NPIX + bn + cB];
    }

    for (int k0 = 0; k0 < KDIM; k0 += 16) {
        *(float2*)&Asd[kA + 0][2 * mA] = make_float2(ra.x, ra.x);
        *(float2*)&Asd[kA + 1][2 * mA] = make_float2(ra.y, ra.y);
        *(float2*)&Asd[kA + 2][2 * mA] = make_float2(ra.z, ra.z);
        *(float2*)&Asd[kA + 3][2 * mA] = make_float2(ra.w, ra.w);
        *(float4*)&Bs[rB][cB] = rb0;
        *(float4*)&Bs[8 + rB][cB] = rb1;
        __syncthreads();

        if (k0 + 16 < KDIM) {
            ra = *(const float4*)&A[(bm + mA) * KDIM + k0 + 16 + kA];
            if (PROJ) {
                float4 a0 = *(const float4*)&B1[(k0 + 16 + rB) * NPIX + bn + cB];
                float4 c0 = *(const float4*)&B2[(k0 + 16 + rB) * NPIX + bn + cB];
                rb0 = make_float4(0.5f*(a0.x+c0.x), 0.5f*(a0.y+c0.y), 0.5f*(a0.z+c0.z), 0.5f*(a0.w+c0.w));
                float4 a1 = *(const float4*)&B1[(k0 + 24 + rB) * NPIX + bn + cB];
                float4 c1 = *(const float4*)&B2[(k0 + 24 + rB) * NPIX + bn + cB];
                rb1 = make_float4(0.5f*(a1.x+c1.x), 0.5f*(a1.y+c1.y), 0.5f*(a1.z+c1.z), 0.5f*(a1.w+c1.w));
            } else {
                rb0 = *(const float4*)&B1[(k0 + 16 + rB) * NPIX + bn + cB];
                rb1 = *(const float4*)&B1[(k0 + 24 + rB) * NPIX + bn + cB];
            }
        }

        #pragma unroll
        for (int kk = 0; kk < 16; kk++) {
            U2 ad0, ad1, bb0, bb1;
            ad0.v4 = *(const float4*)&Asd[kk][ty * 8];       // (a0,a0,a1,a1)
            ad1.v4 = *(const float4*)&Asd[kk][ty * 8 + 4];   // (a2,a2,a3,a3)
            bb0.v4 = *(const float4*)&Bs[kk][tx * 4];
            bb1.v4 = *(const float4*)&Bs[kk][64 + tx * 4];
            acc[0][0] = f2fma(ad0.u[0], bb0.u[0], acc[0][0]);
            acc[0][1] = f2fma(ad0.u[0], bb0.u[1], acc[0][1]);
            acc[0][2] = f2fma(ad0.u[0], bb1.u[0], acc[0][2]);
            acc[0][3] = f2fma(ad0.u[0], bb1.u[1], acc[0][3]);
            acc[1][0] = f2fma(ad0.u[1], bb0.u[0], acc[1][0]);
            acc[1][1] = f2fma(ad0.u[1], bb0.u[1], acc[1][1]);
            acc[1][2] = f2fma(ad0.u[1], bb1.u[0], acc[1][2]);
            acc[1][3] = f2fma(ad0.u[1], bb1.u[1], acc[1][3]);
            acc[2][0] = f2fma(ad1.u[0], bb0.u[0], acc[2][0]);
            acc[2][1] = f2fma(ad1.u[0], bb0.u[1], acc[2][1]);
            acc[2][2] = f2fma(ad1.u[0], bb1.u[0], acc[2][2]);
            acc[2][3] = f2fma(ad1.u[0], bb1.u[1], acc[2][3]);
            acc[3][0] = f2fma(ad1.u[1], bb0.u[0], acc[3][0]);
            acc[3][1] = f2fma(ad1.u[1], bb0.u[1], acc[3][1]);
            acc[3][2] = f2fma(ad1.u[1], bb1.u[0], acc[3][2]);
            acc[3][3] = f2fma(ad1.u[1], bb1.u[1], acc[3][3]);
        }
        __syncthreads();
    }

    #pragma unroll
    for (int i = 0; i < 4; i++) {
        int row = bm + ty * 4 + i;
        float bs = bias[row];
        float2 c0 = f2unpack(acc[i][0]), c1 = f2unpack(acc[i][1]);
        float2 c2 = f2unpack(acc[i][2]), c3 = f2unpack(acc[i][3]);
        float4 o0 = make_float4(c0.x + bs, c0.y + bs, c1.x + bs, c1.y + bs);
        float4 o1 = make_float4(c2.x + bs, c2.y + bs, c3.x + bs, c3.y + bs);
        *(float4*)&C[row * NPIX + bn + tx * 4] = o0;
        *(float4*)&C[row * NPIX + bn + 64 + tx * 4] = o1;
    }
}

// ---------------- Windowed attention (mixed-QT for SMSP balance) ----------------
// grid (16 windows, 8 heads, 2 branches); 384 threads = 12 warps.
// Warps 0-3: 3 queries/lane (96 q), warps 4-11: 2 q/lane (64 q) -> 896 >= 784.
// Per-SMSP f2fma load balanced: (72+48+48) everywhere.
template<int QT>
__device__ __forceinline__ void attn_work(
    const float* __restrict__ qkv, float* __restrict__ outp,
    const float* sk, const float* sv, const float* sb,
    int qbase, int lane, int w, int h, int br)
{
    int l[QT], p[QT], bro[QT];
    bool valid[QT];
    #pragma unroll
    for (int t = 0; t < QT; t++) {
        int li = qbase + lane + 32 * t;
        valid[t] = li < LTOK;
        int lc = valid[t] ? li : (LTOK - 1);
        l[t] = lc;
        p[t] = br ? ((lc / 7) * 112 + w * 7 + (lc % 7)) : (w * LTOK + lc);
        bro[t] = (br ? (lc % 7) : (lc / 112)) * 7;
    }

    unsigned long long q[QT][12], o[QT][12];
    float s[QT];
    #pragma unroll
    for (int t = 0; t < QT; t++) {
        s[t] = 0.f;
        #pragma unroll
        for (int j = 0; j < 12; j++) {
            float a0 = qkv[(h * HDIM + 2 * j) * HWPIX + p[t]] * SCALE_F;
            float a1 = qkv[(h * HDIM + 2 * j + 1) * HWPIX + p[t]] * SCALE_F;
            q[t][j] = f2pack(a0, a1);
            o[t][j] = 0ull;
        }
    }

    int grow = 0, gcnt = 0;
    for (int m0 = 0; m0 < LTOK; m0 += 7) {
        float rb[QT];
        #pragma unroll
        for (int t = 0; t < QT; t++) rb[t] = sb[bro[t] + grow];
        #pragma unroll
        for (int j = 0; j < 7; j++) {
            int m = m0 + j;
            U6 kk;
            const float4* kp = (const float4*)(sk + m * HDIM);
            #pragma unroll
            for (int u = 0; u < 6; u++) kk.v4[u] = kp[u];

            unsigned long long acc0[QT], acc1[QT];
            #pragma unroll
            for (int t = 0; t < QT; t++) { acc0[t] = 0ull; acc1[t] = 0ull; }
            #pragma unroll
            for (int u = 0; u < 6; u++) {
                #pragma unroll
                for (int t = 0; t < QT; t++) {
                    acc0[t] = f2fma(q[t][2 * u],     kk.u[2 * u],     acc0[t]);
                    acc1[t] = f2fma(q[t][2 * u + 1], kk.u[2 * u + 1], acc1[t]);
                }
            }
            float e[QT];
            #pragma unroll
            for (int t = 0; t < QT; t++) {
                float bias = br ? sb[bro[t] + j] : rb[t];
                float2 fa = f2unpack(acc0[t]), fb = f2unpack(acc1[t]);
                float lg = fa.x + fa.y + fb.x + fb.y + bias;
                e[t] = __expf(lg);
                s[t] += e[t];
            }
            U6 vv;
            const float4* vp = (const float4*)(sv + m * HDIM);
            #pragma unroll
            for (int u = 0; u < 6; u++) vv.v4[u] = vp[u];
            #pragma unroll
            for (int t = 0; t < QT; t++) {
                unsigned long long pp = f2pack(e[t], e[t]);
                #pragma unroll
                for (int u = 0; u < 12; u++)
                    o[t][u] = f2fma(pp, vv.u[u], o[t][u]);
            }
        }
        if (++gcnt == 16) { gcnt = 0; grow++; }
    }

    #pragma unroll
    for (int t = 0; t < QT; t++) {
        float inv = 1.f / s[t];
        if (valid[t]) {
            #pragma unroll
            for (int j = 0; j < 12; j++) {
                float2 f = f2unpack(o[t][j]);
                outp[(h * HDIM + 2 * j)     * HWPIX + p[t]] = f.x * inv;
                outp[(h * HDIM + 2 * j + 1) * HWPIX + p[t]] = f.y * inv;
            }
        }
    }
}

__global__ __launch_bounds__(384, 1) void attn_kernel(
    const float* __restrict__ tab_h, const float* __restrict__ tab_v)
{
    extern __shared__ float sm[];
    float* sk = sm;                       // [784*24]
    float* sv = sm + LTOK * HDIM;         // [784*24]
    float* sb = sm + 2 * LTOK * HDIM;     // [49]

    const int w = blockIdx.x, h = blockIdx.y, br = blockIdx.z;
    const float* qkv = br ? g_qkv_v : g_qkv_h;
    float* outp = br ? g_att_v : g_att_h;
    const float* tab = br ? tab_v : tab_h;
    const int tid = threadIdx.x;

    if (tid < 49) {
        int r1 = tid / 7, r2 = tid % 7, off = r1 - r2 + 6;
        sb[tid] = br ? tab[(6 * 13 + off) * NHEAD + h]
                     : tab[(off * 13 + 6) * NHEAD + h];
    }
    for (int idx = tid; idx < LTOK * HDIM; idx += 384) {
        int d = idx / LTOK, m = idx % LTOK;
        int pix = br ? ((m / 7) * 112 + w * 7 + (m % 7)) : (w * LTOK + m);
        sk[m * HDIM + d] = qkv[(192 + h * HDIM + d) * HWPIX + pix];
        sv[m * HDIM + d] = qkv[(384 + h * HDIM + d) * HWPIX + pix];
    }
    __syncthreads();

    const int warp = tid >> 5, lane = tid & 31;
    if (warp < 4) {
        attn_work<3>(qkv, outp, sk, sv, sb, warp * 96, lane, w, h, br);
    } else {
        attn_work<2>(qkv, outp, sk, sv, sb, 384 + (warp - 4) * 64, lane, w, h, br);
    }
}

// ---------------- LePE: out = x + gelu(dwconv3x3(x) + b), 4 px/thread ----------------
__global__ __launch_bounds__(256) void lepe_kernel(
    const float* __restrict__ att, const float* __restrict__ wgt,
    const float* __restrict__ bias, float* __restrict__ out)
{
    int t = blockIdx.x * blockDim.x + threadIdx.x;
    if (t >= Cdim * (HWPIX / 4)) return;
    int c = t / (HWPIX / 4);
    int r = t % (HWPIX / 4);
    int y = r / 28, x4 = (r % 28) * 4;
    const float* base = att + c * HWPIX;

    float wv[9];
    #pragma unroll
    for (int i = 0; i < 9; i++) wv[i] = wgt[c * 9 + i];
    float bsv = bias[c];
    float acc0 = bsv, acc1 = bsv, acc2 = bsv, acc3 = bsv;

    #pragma unroll
    for (int ky = 0; ky < 3; ky++) {
        int yy = y + ky - 1;
        if (yy < 0 || yy >= 112) continue;
        const float* rp = base + yy * 112 + x4;
        float4 mid = *(const float4*)rp;
        float lf = (x4 > 0)   ? rp[-1] : 0.f;
        float rt = (x4 < 108) ? rp[4]  : 0.f;
        float w0 = wv[ky * 3 + 0], w1 = wv[ky * 3 + 1], w2 = wv[ky * 3 + 2];
        acc0 += w0 * lf    + w1 * mid.x + w2 * mid.y;
        acc1 += w0 * mid.x + w1 * mid.y + w2 * mid.z;
        acc2 += w0 * mid.y + w1 * mid.z + w2 * mid.w;
        acc3 += w0 * mid.z + w1 * mid.w + w2 * rt;
    }

    float4 in = *(const float4*)(base + y * 112 + x4);
    float4 o;
    o.x = in.x + 0.5f * acc0 * (1.f + erff(acc0 * 0.70710678118654752f));
    o.y = in.y + 0.5f * acc1 * (1.f + erff(acc1 * 0.70710678118654752f));
    o.z = in.z + 0.5f * acc2 * (1.f + erff(acc2 * 0.70710678118654752f));
    o.w = in.w + 0.5f * acc3 * (1.f + erff(acc3 * 0.70710678118654752f));
    *(float4*)(out + c * HWPIX + y * 112 + x4) = o;
}

// ---------------- launch ----------------
extern "C" void kernel_launch(void* const* d_in, const int* in_sizes, int n_in,
                              void* d_out, int out_size)
{
    const float* x        = (const float*)d_in[0];
    const float* qkv_h_w  = (const float*)d_in[1];
    const float* qkv_h_b  = (const float*)d_in[2];
    const float* qkv_v_w  = (const float*)d_in[3];
    const float* qkv_v_b  = (const float*)d_in[4];
    const float* proj_w   = (const float*)d_in[5];
    const float* proj_b   = (const float*)d_in[6];
    const float* lepe_h_w = (const float*)d_in[7];
    const float* lepe_h_b = (const float*)d_in[8];
    const float* lepe_v_w = (const float*)d_in[9];
    const float* lepe_v_b = (const float*)d_in[10];
    const float* tab_h    = (const float*)d_in[11];
    const float* tab_v    = (const float*)d_in[12];
    float* out = (float*)d_out;

    float *qh, *qv, *ah, *av, *lh, *lv;
    cudaGetSymbolAddress((void**)&qh, g_qkv_h);
    cudaGetSymbolAddress((void**)&qv, g_qkv_v);
    cudaGetSymbolAddress((void**)&ah, g_att_h);
    cudaGetSymbolAddress((void**)&av, g_att_v);
    cudaGetSymbolAddress((void**)&lh, g_lep_h);
    cudaGetSymbolAddress((void**)&lv, g_lep_v);

    // QKV GEMMs
    dim3 gq(NPIX / 128, M_QKV / 64);
    gemm_t<false><<<gq, 256>>>(qkv_h_w, x, nullptr, qkv_h_b, qh);
    gemm_t<false><<<gq, 256>>>(qkv_v_w, x, nullptr, qkv_v_b, qv);

    // Attention (both branches)
    static const int smem_bytes = (2 * LTOK * HDIM + 64) * sizeof(float);
    cudaFuncSetAttribute(attn_kernel,
                         cudaFuncAttributeMaxDynamicSharedMemorySize, smem_bytes);
    dim3 ga(16, NHEAD, 2);
    attn_kernel<<<ga, 384, smem_bytes>>>(tab_h, tab_v);

    // LePE
    int nthr = Cdim * (HWPIX / 4);
    int nblk = (nthr + 255) / 256;
    lepe_kernel<<<nblk, 256>>>(ah, lepe_h_w, lepe_h_b, lh);
    lepe_kernel<<<nblk, 256>>>(av, lepe_v_w, lepe_v_b, lv);

    // Fused average + projection
    dim3 gp(NPIX / 128, M_PROJ / 64);
    gemm_t<true><<<gp, 256>>>(proj_w, lh, lv, proj_b, out);
}

// round 5
// speedup vs baseline: 1.7131x; 1.7131x over previous
#include <cuda_runtime.h>
#include <cuda_bf16.h>
#include <cstdint>
#include <math.h>

#define Cdim   192
#define NHEAD  8
#define HDIM   24
#define HWPIX  12544          // 112*112
#define LTOK   784            // 7*112
#define KDIM   192
#define NPIX   12544
#define M_QKV  576
#define M_PROJ 192
#define SCALE_F 0.20412414523193154f  // 24^-0.5

// ---------------- scratch (device globals; no allocation) ----------------
__device__ float g_qkv_h[M_QKV * HWPIX];
__device__ float g_qkv_v[M_QKV * HWPIX];
__device__ float g_att_h[Cdim * HWPIX];
__device__ float g_att_v[Cdim * HWPIX];
__device__ float g_lep_h[Cdim * HWPIX];
__device__ float g_lep_v[Cdim * HWPIX];

// ---------------- f32x2 helpers (GEMM) ----------------
__device__ __forceinline__ unsigned long long f2pack(float a, float b) {
    unsigned long long r;
    asm("mov.b64 %0, {%1,%2};" : "=l"(r) : "f"(a), "f"(b));
    return r;
}
__device__ __forceinline__ unsigned long long f2fma(unsigned long long a,
                                                    unsigned long long b,
                                                    unsigned long long c) {
    unsigned long long r;
    asm("fma.rn.f32x2 %0, %1, %2, %3;" : "=l"(r) : "l"(a), "l"(b), "l"(c));
    return r;
}
__device__ __forceinline__ float2 f2unpack(unsigned long long a) {
    float2 f;
    asm("mov.b64 {%0,%1}, %2;" : "=f"(f.x), "=f"(f.y) : "l"(a));
    return f;
}

// ---------------- GEMM: C[M,N] = A[M,K] * B[K,N] + bias (R2 measured) ----------------
template<bool PROJ>
__global__ __launch_bounds__(256) void gemm_t(
    const float* __restrict__ A, const float* __restrict__ B1,
    const float* __restrict__ B2, const float* __restrict__ bias,
    float* __restrict__ C)
{
    __shared__ float As[16][68];
    __shared__ float Bs[16][128];
    const int bm = blockIdx.y * 64, bn = blockIdx.x * 128;
    const int tid = threadIdx.x;
    const int tx = tid & 15, ty = tid >> 4;
    const int mA = tid >> 2, kA = (tid & 3) * 4;
    const int rB = tid >> 5, cB = (tid & 31) * 4;

    unsigned long long acc[4][4];
    #pragma unroll
    for (int i = 0; i < 4; i++)
        #pragma unroll
        for (int j = 0; j < 4; j++) acc[i][j] = 0ull;

    float4 ra, rb0, rb1;
    ra = *(const float4*)&A[(bm + mA) * KDIM + kA];
    if (PROJ) {
        float4 a0 = *(const float4*)&B1[rB * NPIX + bn + cB];
        float4 c0 = *(const float4*)&B2[rB * NPIX + bn + cB];
        rb0 = make_float4(0.5f*(a0.x+c0.x), 0.5f*(a0.y+c0.y), 0.5f*(a0.z+c0.z), 0.5f*(a0.w+c0.w));
        float4 a1 = *(const float4*)&B1[(8 + rB) * NPIX + bn + cB];
        float4 c1 = *(const float4*)&B2[(8 + rB) * NPIX + bn + cB];
        rb1 = make_float4(0.5f*(a1.x+c1.x), 0.5f*(a1.y+c1.y), 0.5f*(a1.z+c1.z), 0.5f*(a1.w+c1.w));
    } else {
        rb0 = *(const float4*)&B1[rB * NPIX + bn + cB];
        rb1 = *(const float4*)&B1[(8 + rB) * NPIX + bn + cB];
    }

    for (int k0 = 0; k0 < KDIM; k0 += 16) {
        As[kA + 0][mA] = ra.x; As[kA + 1][mA] = ra.y;
        As[kA + 2][mA] = ra.z; As[kA + 3][mA] = ra.w;
        *(float4*)&Bs[rB][cB] = rb0;
        *(float4*)&Bs[8 + rB][cB] = rb1;
        __syncthreads();

        if (k0 + 16 < KDIM) {
            ra = *(const float4*)&A[(bm + mA) * KDIM + k0 + 16 + kA];
            if (PROJ) {
                float4 a0 = *(const float4*)&B1[(k0 + 16 + rB) * NPIX + bn + cB];
                float4 c0 = *(const float4*)&B2[(k0 + 16 + rB) * NPIX + bn + cB];
                rb0 = make_float4(0.5f*(a0.x+c0.x), 0.5f*(a0.y+c0.y), 0.5f*(a0.z+c0.z), 0.5f*(a0.w+c0.w));
                float4 a1 = *(const float4*)&B1[(k0 + 24 + rB) * NPIX + bn + cB];
                float4 c1 = *(const float4*)&B2[(k0 + 24 + rB) * NPIX + bn + cB];
                rb1 = make_float4(0.5f*(a1.x+c1.x), 0.5f*(a1.y+c1.y), 0.5f*(a1.z+c1.z), 0.5f*(a1.w+c1.w));
            } else {
                rb0 = *(const float4*)&B1[(k0 + 16 + rB) * NPIX + bn + cB];
                rb1 = *(const float4*)&B1[(k0 + 24 + rB) * NPIX + bn + cB];
            }
        }

        #pragma unroll
        for (int kk = 0; kk < 16; kk++) {
            float4 av  = *(const float4*)&As[kk][ty * 4];
            float4 bv0 = *(const float4*)&Bs[kk][tx * 4];
            float4 bv1 = *(const float4*)&Bs[kk][64 + tx * 4];
            unsigned long long b00 = f2pack(bv0.x, bv0.y);
            unsigned long long b01 = f2pack(bv0.z, bv0.w);
            unsigned long long b10 = f2pack(bv1.x, bv1.y);
            unsigned long long b11 = f2pack(bv1.z, bv1.w);
            float aa[4] = {av.x, av.y, av.z, av.w};
            #pragma unroll
            for (int i = 0; i < 4; i++) {
                unsigned long long pa = f2pack(aa[i], aa[i]);
                acc[i][0] = f2fma(pa, b00, acc[i][0]);
                acc[i][1] = f2fma(pa, b01, acc[i][1]);
                acc[i][2] = f2fma(pa, b10, acc[i][2]);
                acc[i][3] = f2fma(pa, b11, acc[i][3]);
            }
        }
        __syncthreads();
    }

    #pragma unroll
    for (int i = 0; i < 4; i++) {
        int row = bm + ty * 4 + i;
        float bs = bias[row];
        float2 c0 = f2unpack(acc[i][0]), c1 = f2unpack(acc[i][1]);
        float2 c2 = f2unpack(acc[i][2]), c3 = f2unpack(acc[i][3]);
        float4 o0 = make_float4(c0.x + bs, c0.y + bs, c1.x + bs, c1.y + bs);
        float4 o1 = make_float4(c2.x + bs, c2.y + bs, c3.x + bs, c3.y + bs);
        *(float4*)&C[row * NPIX + bn + tx * 4] = o0;
        *(float4*)&C[row * NPIX + bn + 64 + tx * 4] = o1;
    }
}

// ============================================================================
// mma.sync bf16 flash attention (hi/lo compensated, fp32 accumulate)
// ============================================================================
#define KT   56      // keys per smem tile
#define NKT  14      // 784/56
#define KSTR 36      // K smem row stride (halves)
#define VSTR 72      // V^T smem row stride (halves)

__device__ __forceinline__ void mma_bf16(float* c,
    uint32_t a0, uint32_t a1, uint32_t a2, uint32_t a3,
    uint32_t b0, uint32_t b1)
{
    asm volatile("mma.sync.aligned.m16n8k16.row.col.f32.bf16.bf16.f32 "
        "{%0,%1,%2,%3}, {%4,%5,%6,%7}, {%8,%9}, {%0,%1,%2,%3};"
        : "+f"(c[0]), "+f"(c[1]), "+f"(c[2]), "+f"(c[3])
        : "r"(a0), "r"(a1), "r"(a2), "r"(a3), "r"(b0), "r"(b1));
}
// pack two f32 -> bf16x2 (lo element in low half)
__device__ __forceinline__ uint32_t bfp(float lo_el, float hi_el) {
    uint32_t r;
    asm("cvt.rn.bf16x2.f32 %0, %1, %2;" : "=r"(r) : "f"(hi_el), "f"(lo_el));
    return r;
}
__device__ __forceinline__ float bflo(uint32_t p) { return __uint_as_float(p << 16); }
__device__ __forceinline__ float bfhi(uint32_t p) { return __uint_as_float(p & 0xFFFF0000u); }

__global__ __launch_bounds__(224, 2) void attn_mma(
    const float* __restrict__ tab_h, const float* __restrict__ tab_v)
{
    __shared__ __align__(16) unsigned short sKhi[KT * KSTR];
    __shared__ __align__(16) unsigned short sKlo[KT * KSTR];
    __shared__ __align__(16) unsigned short sVhi[HDIM * VSTR];
    __shared__ __align__(16) unsigned short sVlo[HDIM * VSTR];
    __shared__ float sb[56];

    const int tid = threadIdx.x;
    const int w = blockIdx.x, h = blockIdx.y, br = blockIdx.z;
    const float* __restrict__ qkv = br ? g_qkv_v : g_qkv_h;
    float* __restrict__ outp = br ? g_att_v : g_att_h;
    const float* __restrict__ tab = br ? tab_v : tab_h;

    if (tid < 49) {
        int r1 = tid / 7, r2 = tid % 7, off = r1 - r2 + 6;
        sb[tid] = br ? tab[(6 * 13 + off) * NHEAD + h]
                     : tab[(off * 13 + 6) * NHEAD + h];
    }
    // zero-fill pad regions (dims 24..35 of K rows, keys 56..63 of V rows) — zero all
    for (int i = tid; i < KT * KSTR; i += 224) { sKhi[i] = 0; sKlo[i] = 0; }
    for (int i = tid; i < HDIM * VSTR; i += 224) { sVhi[i] = 0; sVlo[i] = 0; }

    const int warp = tid >> 5, lane = tid & 31;
    const int g = lane >> 2, q = lane & 3;
    const int d0 = 2 * q;

    for (int mi = 0; mi < 7; mi++) {
        const int mtile = mi * 7 + warp;           // 0..48
        const int r0 = mtile * 16 + g, r1 = r0 + 8;
        const int pix0 = br ? ((r0 / 7) * 112 + w * 7 + (r0 % 7)) : (w * LTOK + r0);
        const int pix1 = br ? ((r1 / 7) * 112 + w * 7 + (r1 % 7)) : (w * LTOK + r1);
        const int bro0 = (br ? (r0 % 7) : (r0 / 112)) * 7;
        const int bro1 = (br ? (r1 % 7) : (r1 / 112)) * 7;

        // --- Q fragments (hi/lo), pre-scaled ---
        uint32_t qh[6], ql[6];
        #pragma unroll
        for (int p = 0; p < 3; p++) {
            int d = d0 + 8 * p;
            float a0v = qkv[(h * HDIM + d)     * HWPIX + pix0] * SCALE_F;
            float a1v = qkv[(h * HDIM + d + 1) * HWPIX + pix0] * SCALE_F;
            float b0v = qkv[(h * HDIM + d)     * HWPIX + pix1] * SCALE_F;
            float b1v = qkv[(h * HDIM + d + 1) * HWPIX + pix1] * SCALE_F;
            uint32_t hA = bfp(a0v, a1v), hB = bfp(b0v, b1v);
            qh[2 * p] = hA; qh[2 * p + 1] = hB;
            ql[2 * p]     = bfp(a0v - bflo(hA), a1v - bfhi(hA));
            ql[2 * p + 1] = bfp(b0v - bflo(hB), b1v - bfhi(hB));
        }

        float o[3][4];
        #pragma unroll
        for (int nd = 0; nd < 3; nd++)
            #pragma unroll
            for (int i = 0; i < 4; i++) o[nd][i] = 0.f;
        float rs0 = 0.f, rs1 = 0.f;

        for (int kt = 0; kt < NKT; kt++) {
            __syncthreads();
            // --- cooperative K/V tile load + bf16 hi/lo split ---
            #pragma unroll
            for (int i = 0; i < 6; i++) {
                int idx = tid + i * 224;           // 1344 = 56*24
                int d = idx / KT, k = idx - d * KT;
                int m = kt * KT + k;
                int pix = br ? ((m / 7) * 112 + w * 7 + (m % 7)) : (w * LTOK + m);
                float kv = qkv[(192 + h * HDIM + d) * HWPIX + pix];
                float vv = qkv[(384 + h * HDIM + d) * HWPIX + pix];
                __nv_bfloat16 kh = __float2bfloat16(kv);
                __nv_bfloat16 vh = __float2bfloat16(vv);
                sKhi[k * KSTR + d] = __bfloat16_as_ushort(kh);
                sKlo[k * KSTR + d] = __bfloat16_as_ushort(__float2bfloat16(kv - __bfloat162float(kh)));
                sVhi[d * VSTR + k] = __bfloat16_as_ushort(vh);
                sVlo[d * VSTR + k] = __bfloat16_as_ushort(__float2bfloat16(vv - __bfloat162float(vh)));
            }
            __syncthreads();

            float bh0 = 0.f, bh1 = 0.f;
            if (!br) { bh0 = sb[bro0 + (kt >> 1)]; bh1 = sb[bro1 + (kt >> 1)]; }

            #pragma unroll
            for (int ks = 0; ks < 4; ks++) {
                const int nt0 = 2 * ks, nt1 = nt0 + 1;
                const bool has1 = (nt1 < 7);
                float sA[4] = {0.f, 0.f, 0.f, 0.f};
                float sB[4] = {0.f, 0.f, 0.f, 0.f};

                // S mma for ntile nt0
                {
                    int kb = (nt0 * 8 + g) * KSTR + d0;
                    uint32_t kh00 = *(const uint32_t*)&sKhi[kb];
                    uint32_t kh01 = *(const uint32_t*)&sKhi[kb + 8];
                    uint32_t kh10 = *(const uint32_t*)&sKhi[kb + 16];
                    uint32_t kh11 = *(const uint32_t*)&sKhi[kb + 24];
                    uint32_t kl00 = *(const uint32_t*)&sKlo[kb];
                    uint32_t kl01 = *(const uint32_t*)&sKlo[kb + 8];
                    uint32_t kl10 = *(const uint32_t*)&sKlo[kb + 16];
                    uint32_t kl11 = *(const uint32_t*)&sKlo[kb + 24];
                    mma_bf16(sA, qh[0], qh[1], qh[2], qh[3], kh00, kh01);
                    mma_bf16(sA, ql[0], ql[1], ql[2], ql[3], kh00, kh01);
                    mma_bf16(sA, qh[0], qh[1], qh[2], qh[3], kl00, kl01);
                    mma_bf16(sA, qh[4], qh[5], 0u, 0u, kh10, kh11);
                    mma_bf16(sA, ql[4], ql[5], 0u, 0u, kh10, kh11);
                    mma_bf16(sA, qh[4], qh[5], 0u, 0u, kl10, kl11);
                }
                if (has1) {
                    int kb = (nt1 * 8 + g) * KSTR + d0;
                    uint32_t kh00 = *(const uint32_t*)&sKhi[kb];
                    uint32_t kh01 = *(const uint32_t*)&sKhi[kb + 8];
                    uint32_t kh10 = *(const uint32_t*)&sKhi[kb + 16];
                    uint32_t kh11 = *(const uint32_t*)&sKhi[kb + 24];
                    uint32_t kl00 = *(const uint32_t*)&sKlo[kb];
                    uint32_t kl01 = *(const uint32_t*)&sKlo[kb + 8];
                    uint32_t kl10 = *(const uint32_t*)&sKlo[kb + 16];
                    uint32_t kl11 = *(const uint32_t*)&sKlo[kb + 24];
                    mma_bf16(sB, qh[0], qh[1], qh[2], qh[3], kh00, kh01);
                    mma_bf16(sB, ql[0], ql[1], ql[2], ql[3], kh00, kh01);
                    mma_bf16(sB, qh[0], qh[1], qh[2], qh[3], kl00, kl01);
                    mma_bf16(sB, qh[4], qh[5], 0u, 0u, kh10, kh11);
                    mma_bf16(sB, ql[4], ql[5], 0u, 0u, kh10, kh11);
                    mma_bf16(sB, qh[4], qh[5], 0u, 0u, kl10, kl11);
                }

                // bias + exp
                float eA0, eA1, eA2, eA3, eB0 = 0.f, eB1 = 0.f, eB2 = 0.f, eB3 = 0.f;
                if (!br) {
                    eA0 = __expf(sA[0] + bh0); eA1 = __expf(sA[1] + bh0);
                    eA2 = __expf(sA[2] + bh1); eA3 = __expf(sA[3] + bh1);
                    if (has1) {
                        eB0 = __expf(sB[0] + bh0); eB1 = __expf(sB[1] + bh0);
                        eB2 = __expf(sB[2] + bh1); eB3 = __expf(sB[3] + bh1);
                    }
                } else {
                    int i0 = (nt0 + d0) % 7;
                    int i1 = i0 + 1; if (i1 == 7) i1 = 0;
                    int j1 = i1 + 1; if (j1 == 7) j1 = 0;
                    eA0 = __expf(sA[0] + sb[bro0 + i0]); eA1 = __expf(sA[1] + sb[bro0 + i1]);
                    eA2 = __expf(sA[2] + sb[bro1 + i0]); eA3 = __expf(sA[3] + sb[bro1 + i1]);
                    if (has1) {
                        eB0 = __expf(sB[0] + sb[bro0 + i1]); eB1 = __expf(sB[1] + sb[bro0 + j1]);
                        eB2 = __expf(sB[2] + sb[bro1 + i1]); eB3 = __expf(sB[3] + sb[bro1 + j1]);
                    }
                }
                rs0 += eA0 + eA1 + eB0 + eB1;
                rs1 += eA2 + eA3 + eB2 + eB3;

                // P fragments (A-frag layout == S D-frag layout)
                uint32_t pa0 = bfp(eA0, eA1), pa1 = bfp(eA2, eA3);
                uint32_t pa2 = has1 ? bfp(eB0, eB1) : 0u;
                uint32_t pa3 = has1 ? bfp(eB2, eB3) : 0u;
                uint32_t pl0 = bfp(eA0 - bflo(pa0), eA1 - bfhi(pa0));
                uint32_t pl1 = bfp(eA2 - bflo(pa1), eA3 - bfhi(pa1));
                uint32_t pl2 = has1 ? bfp(eB0 - bflo(pa2), eB1 - bfhi(pa2)) : 0u;
                uint32_t pl3 = has1 ? bfp(eB2 - bflo(pa3), eB3 - bfhi(pa3)) : 0u;

                // O += P @ V
                #pragma unroll
                for (int nd = 0; nd < 3; nd++) {
                    int vb = (nd * 8 + g) * VSTR + ks * 16 + d0;
                    uint32_t vh0 = *(const uint32_t*)&sVhi[vb];
                    uint32_t vh1 = *(const uint32_t*)&sVhi[vb + 8];
                    uint32_t vl0 = *(const uint32_t*)&sVlo[vb];
                    uint32_t vl1 = *(const uint32_t*)&sVlo[vb + 8];
                    mma_bf16(o[nd], pa0, pa1, pa2, pa3, vh0, vh1);
                    mma_bf16(o[nd], pl0, pl1, pl2, pl3, vh0, vh1);
                    mma_bf16(o[nd], pa0, pa1, pa2, pa3, vl0, vl1);
                }
            }
        }

        // row-sum reduce across the 4-lane quad and write out
        rs0 += __shfl_xor_sync(0xFFFFFFFFu, rs0, 1);
        rs0 += __shfl_xor_sync(0xFFFFFFFFu, rs0, 2);
        rs1 += __shfl_xor_sync(0xFFFFFFFFu, rs1, 1);
        rs1 += __shfl_xor_sync(0xFFFFFFFFu, rs1, 2);
        float inv0 = 1.f / rs0, inv1 = 1.f / rs1;
        #pragma unroll
        for (int nd = 0; nd < 3; nd++) {
            int d = nd * 8 + d0;
            outp[(h * HDIM + d)     * HWPIX + pix0] = o[nd][0] * inv0;
            outp[(h * HDIM + d + 1) * HWPIX + pix0] = o[nd][1] * inv0;
            outp[(h * HDIM + d)     * HWPIX + pix1] = o[nd][2] * inv1;
            outp[(h * HDIM + d + 1) * HWPIX + pix1] = o[nd][3] * inv1;
        }
    }
}

// ---------------- LePE: out = x + gelu(dwconv3x3(x) + b), 4 px/thread ----------------
__global__ __launch_bounds__(256) void lepe_kernel(
    const float* __restrict__ att, const float* __restrict__ wgt,
    const float* __restrict__ bias, float* __restrict__ out)
{
    int t = blockIdx.x * blockDim.x + threadIdx.x;
    if (t >= Cdim * (HWPIX / 4)) return;
    int c = t / (HWPIX / 4);
    int r = t % (HWPIX / 4);
    int y = r / 28, x4 = (r % 28) * 4;
    const float* base = att + c * HWPIX;

    float wv[9];
    #pragma unroll
    for (int i = 0; i < 9; i++) wv[i] = wgt[c * 9 + i];
    float bsv = bias[c];
    float acc0 = bsv, acc1 = bsv, acc2 = bsv, acc3 = bsv;

    #pragma unroll
    for (int ky = 0; ky < 3; ky++) {
        int yy = y + ky - 1;
        if (yy < 0 || yy >= 112) continue;
        const float* rp = base + yy * 112 + x4;
        float4 mid = *(const float4*)rp;
        float lf = (x4 > 0)   ? rp[-1] : 0.f;
        float rt = (x4 < 108) ? rp[4]  : 0.f;
        float w0 = wv[ky * 3 + 0], w1 = wv[ky * 3 + 1], w2 = wv[ky * 3 + 2];
        acc0 += w0 * lf    + w1 * mid.x + w2 * mid.y;
        acc1 += w0 * mid.x + w1 * mid.y + w2 * mid.z;
        acc2 += w0 * mid.y + w1 * mid.z + w2 * mid.w;
        acc3 += w0 * mid.z + w1 * mid.w + w2 * rt;
    }

    float4 in = *(const float4*)(base + y * 112 + x4);
    float4 o;
    o.x = in.x + 0.5f * acc0 * (1.f + erff(acc0 * 0.70710678118654752f));
    o.y = in.y + 0.5f * acc1 * (1.f + erff(acc1 * 0.70710678118654752f));
    o.z = in.z + 0.5f * acc2 * (1.f + erff(acc2 * 0.70710678118654752f));
    o.w = in.w + 0.5f * acc3 * (1.f + erff(acc3 * 0.70710678118654752f));
    *(float4*)(out + c * HWPIX + y * 112 + x4) = o;
}

// ---------------- launch ----------------
extern "C" void kernel_launch(void* const* d_in, const int* in_sizes, int n_in,
                              void* d_out, int out_size)
{
    const float* x        = (const float*)d_in[0];
    const float* qkv_h_w  = (const float*)d_in[1];
    const float* qkv_h_b  = (const float*)d_in[2];
    const float* qkv_v_w  = (const float*)d_in[3];
    const float* qkv_v_b  = (const float*)d_in[4];
    const float* proj_w   = (const float*)d_in[5];
    const float* proj_b   = (const float*)d_in[6];
    const float* lepe_h_w = (const float*)d_in[7];
    const float* lepe_h_b = (const float*)d_in[8];
    const float* lepe_v_w = (const float*)d_in[9];
    const float* lepe_v_b = (const float*)d_in[10];
    const float* tab_h    = (const float*)d_in[11];
    const float* tab_v    = (const float*)d_in[12];
    float* out = (float*)d_out;

    float *qh, *qv, *ah, *av, *lh, *lv;
    cudaGetSymbolAddress((void**)&qh, g_qkv_h);
    cudaGetSymbolAddress((void**)&qv, g_qkv_v);
    cudaGetSymbolAddress((void**)&ah, g_att_h);
    cudaGetSymbolAddress((void**)&av, g_att_v);
    cudaGetSymbolAddress((void**)&lh, g_lep_h);
    cudaGetSymbolAddress((void**)&lv, g_lep_v);

    // QKV GEMMs
    dim3 gq(NPIX / 128, M_QKV / 64);
    gemm_t<false><<<gq, 256>>>(qkv_h_w, x, nullptr, qkv_h_b, qh);
    gemm_t<false><<<gq, 256>>>(qkv_v_w, x, nullptr, qkv_v_b, qv);

    // mma.sync bf16 attention (both branches)
    dim3 ga(16, NHEAD, 2);
    attn_mma<<<ga, 224>>>(tab_h, tab_v);

    // LePE
    int nthr = Cdim * (HWPIX / 4);
    int nblk = (nthr + 255) / 256;
    lepe_kernel<<<nblk, 256>>>(ah, lepe_h_w, lepe_h_b, lh);
    lepe_kernel<<<nblk, 256>>>(av, lepe_v_w, lepe_v_b, lv);

    // Fused average + projection
    dim3 gp(NPIX / 128, M_PROJ / 64);
    gemm_t<true><<<gp, 256>>>(proj_w, lh, lv, proj_b, out);
}

// round 6
// speedup vs baseline: 1.8881x; 1.1022x over previous
#include <cuda_runtime.h>
#include <cuda_bf16.h>
#include <cstdint>
#include <math.h>

#define Cdim   192
#define NHEAD  8
#define HDIM   24
#define HWPIX  12544          // 112*112
#define LTOK   784            // 7*112
#define GK     192            // gemm K
#define NPIX   12544
#define M_QKV  576
#define M_PROJ 192
#define SCALE_F 0.20412414523193154f  // 24^-0.5

typedef unsigned short ushort_t;

// ---------------- scratch (device globals; no allocation) ----------------
__device__ float g_qkv_h[M_QKV * HWPIX];
__device__ float g_qkv_v[M_QKV * HWPIX];
__device__ float g_att_h[Cdim * HWPIX];
__device__ float g_att_v[Cdim * HWPIX];
__device__ ushort_t g_xhi[GK * NPIX];
__device__ ushort_t g_xlo[GK * NPIX];
__device__ ushort_t g_phi[GK * NPIX];
__device__ ushort_t g_plo[GK * NPIX];
__device__ ushort_t g_whh[M_QKV * GK];
__device__ ushort_t g_whl[M_QKV * GK];
__device__ ushort_t g_wvh[M_QKV * GK];
__device__ ushort_t g_wvl[M_QKV * GK];
__device__ ushort_t g_pwh[M_PROJ * GK];
__device__ ushort_t g_pwl[M_PROJ * GK];

// ---------------- bf16 helpers ----------------
// pack two f32 -> bf16x2 (first arg in low half)
__device__ __forceinline__ uint32_t bfp(float lo_el, float hi_el) {
    uint32_t r;
    asm("cvt.rn.bf16x2.f32 %0, %1, %2;" : "=r"(r) : "f"(hi_el), "f"(lo_el));
    return r;
}
__device__ __forceinline__ float bflo(uint32_t p) { return __uint_as_float(p << 16); }
__device__ __forceinline__ float bfhi(uint32_t p) { return __uint_as_float(p & 0xFFFF0000u); }

__device__ __forceinline__ uint32_t s2u(const void* p) {
    uint32_t a;
    asm("{ .reg .u64 t; cvta.to.shared.u64 t, %1; cvt.u32.u64 %0, t; }" : "=r"(a) : "l"(p));
    return a;
}

__device__ __forceinline__ void mma_bf16(float* c,
    uint32_t a0, uint32_t a1, uint32_t a2, uint32_t a3,
    uint32_t b0, uint32_t b1)
{
    asm volatile("mma.sync.aligned.m16n8k16.row.col.f32.bf16.bf16.f32 "
        "{%0,%1,%2,%3}, {%4,%5,%6,%7}, {%8,%9}, {%0,%1,%2,%3};"
        : "+f"(c[0]), "+f"(c[1]), "+f"(c[2]), "+f"(c[3])
        : "r"(a0), "r"(a1), "r"(a2), "r"(a3), "r"(b0), "r"(b1));
}

__device__ __forceinline__ void ldsm4t(uint32_t& r0, uint32_t& r1,
                                       uint32_t& r2, uint32_t& r3, uint32_t a)
{
    asm volatile("ldmatrix.sync.aligned.m8n8.x4.trans.shared.b16 {%0,%1,%2,%3}, [%4];"
        : "=r"(r0), "=r"(r1), "=r"(r2), "=r"(r3) : "r"(a));
}

// ---------------- split fp32 -> bf16 hi/lo planes (vec4) ----------------
__global__ __launch_bounds__(256) void split_kernel(
    const float4* __restrict__ in, uint2* __restrict__ hi,
    uint2* __restrict__ lo, int n4)
{
    int i = blockIdx.x * blockDim.x + threadIdx.x;
    if (i >= n4) return;
    float4 v = in[i];
    uint32_t h0 = bfp(v.x, v.y);
    uint32_t h1 = bfp(v.z, v.w);
    uint32_t l0 = bfp(v.x - bflo(h0), v.y - bfhi(h0));
    uint32_t l1 = bfp(v.z - bflo(h1), v.w - bfhi(h1));
    hi[i] = make_uint2(h0, h1);
    lo[i] = make_uint2(l0, l1);
}

// ---------------- hi/lo bf16 mma GEMM: C = A[M,K] * B[K,N] + bias ----------------
// block 64M x 128N, 8 warps (4M x 2N), K-step 32, 3-term error compensation.
__global__ __launch_bounds__(256) void gemm_mma(
    const ushort_t* __restrict__ Ahi, const ushort_t* __restrict__ Alo,
    const ushort_t* __restrict__ Bhi, const ushort_t* __restrict__ Blo,
    const float* __restrict__ bias, float* __restrict__ C)
{
    __shared__ __align__(16) ushort_t sBh[32][136];
    __shared__ __align__(16) ushort_t sBl[32][136];
    const int tid = threadIdx.x;
    const int bn = blockIdx.x * 128, bm = blockIdx.y * 64;
    const int wid = tid >> 5, lane = tid & 31;
    const int wm = wid & 3, wn = wid >> 2;
    const int g = lane >> 2, q = lane & 3;
    const int wc = wn * 64;
    const int row0 = bm + wm * 16 + g;
    const int row1 = row0 + 8;

    float acc[8][4];
    #pragma unroll
    for (int i = 0; i < 8; i++)
        #pragma unroll
        for (int j = 0; j < 4; j++) acc[i][j] = 0.f;

    const int rB = tid >> 3;              // 0..31
    const int cB = (tid & 7) * 8;         // 0..56 step 8

    // ldmatrix per-lane base address
    const int lm = lane >> 3, lr = lane & 7;
    const int lkrow = (lm & 1) * 8 + lr;
    const int lncol = wc + (lm >> 1) * 8;
    const uint32_t sbh_base = s2u(&sBh[lkrow][lncol]);
    const uint32_t sbl_base = s2u(&sBl[lkrow][lncol]);

    for (int k0 = 0; k0 < GK; k0 += 32) {
        __syncthreads();
        *(uint4*)&sBh[rB][cB]      = *(const uint4*)&Bhi[(k0 + rB) * NPIX + bn + cB];
        *(uint4*)&sBh[rB][cB + 64] = *(const uint4*)&Bhi[(k0 + rB) * NPIX + bn + cB + 64];
        *(uint4*)&sBl[rB][cB]      = *(const uint4*)&Blo[(k0 + rB) * NPIX + bn + cB];
        *(uint4*)&sBl[rB][cB + 64] = *(const uint4*)&Blo[(k0 + rB) * NPIX + bn + cB + 64];
        __syncthreads();

        #pragma unroll
        for (int hh = 0; hh < 2; hh++) {
            const int kk = k0 + hh * 16;
            uint32_t ah[4], al[4];
            ah[0] = *(const uint32_t*)&Ahi[row0 * GK + kk + 2 * q];
            ah[1] = *(const uint32_t*)&Ahi[row1 * GK + kk + 2 * q];
            ah[2] = *(const uint32_t*)&Ahi[row0 * GK + kk + 2 * q + 8];
            ah[3] = *(const uint32_t*)&Ahi[row1 * GK + kk + 2 * q + 8];
            al[0] = *(const uint32_t*)&Alo[row0 * GK + kk + 2 * q];
            al[1] = *(const uint32_t*)&Alo[row1 * GK + kk + 2 * q];
            al[2] = *(const uint32_t*)&Alo[row0 * GK + kk + 2 * q + 8];
            al[3] = *(const uint32_t*)&Alo[row1 * GK + kk + 2 * q + 8];

            const uint32_t hoff = (uint32_t)(hh * 16 * 136) * 2;
            #pragma unroll
            for (int j = 0; j < 4; j++) {
                uint32_t off = hoff + (uint32_t)(j * 16) * 2;
                uint32_t bh0, bh1, bh2, bh3, bl0, bl1, bl2, bl3;
                ldsm4t(bh0, bh1, bh2, bh3, sbh_base + off);
                ldsm4t(bl0, bl1, bl2, bl3, sbl_base + off);
                float* c0 = acc[2 * j];
                float* c1 = acc[2 * j + 1];
                mma_bf16(c0, ah[0], ah[1], ah[2], ah[3], bh0, bh1);
                mma_bf16(c0, al[0], al[1], al[2], al[3], bh0, bh1);
                mma_bf16(c0, ah[0], ah[1], ah[2], ah[3], bl0, bl1);
                mma_bf16(c1, ah[0], ah[1], ah[2], ah[3], bh2, bh3);
                mma_bf16(c1, al[0], al[1], al[2], al[3], bh2, bh3);
                mma_bf16(c1, ah[0], ah[1], ah[2], ah[3], bl2, bl3);
            }
        }
    }

    const float b0 = bias[row0], b1 = bias[row1];
    #pragma unroll
    for (int nf = 0; nf < 8; nf++) {
        int col = bn + wc + nf * 8 + 2 * q;
        *(float2*)&C[row0 * NPIX + col] = make_float2(acc[nf][0] + b0, acc[nf][1] + b0);
        *(float2*)&C[row1 * NPIX + col] = make_float2(acc[nf][2] + b1, acc[nf][3] + b1);
    }
}

// ============================================================================
// mma.sync bf16 flash attention (R5, unchanged)
// ============================================================================
#define KT   56
#define NKT  14
#define KSTR 36
#define VSTR 72

__global__ __launch_bounds__(224, 2) void attn_mma(
    const float* __restrict__ tab_h, const float* __restrict__ tab_v)
{
    __shared__ __align__(16) ushort_t sKhi[KT * KSTR];
    __shared__ __align__(16) ushort_t sKlo[KT * KSTR];
    __shared__ __align__(16) ushort_t sVhi[HDIM * VSTR];
    __shared__ __align__(16) ushort_t sVlo[HDIM * VSTR];
    __shared__ float sb[56];

    const int tid = threadIdx.x;
    const int w = blockIdx.x, h = blockIdx.y, br = blockIdx.z;
    const float* __restrict__ qkv = br ? g_qkv_v : g_qkv_h;
    float* __restrict__ outp = br ? g_att_v : g_att_h;
    const float* __restrict__ tab = br ? tab_v : tab_h;

    if (tid < 49) {
        int r1 = tid / 7, r2 = tid % 7, off = r1 - r2 + 6;
        sb[tid] = br ? tab[(6 * 13 + off) * NHEAD + h]
                     : tab[(off * 13 + 6) * NHEAD + h];
    }
    for (int i = tid; i < KT * KSTR; i += 224) { sKhi[i] = 0; sKlo[i] = 0; }
    for (int i = tid; i < HDIM * VSTR; i += 224) { sVhi[i] = 0; sVlo[i] = 0; }

    const int warp = tid >> 5, lane = tid & 31;
    const int g = lane >> 2, q = lane & 3;
    const int d0 = 2 * q;

    for (int mi = 0; mi < 7; mi++) {
        const int mtile = mi * 7 + warp;
        const int r0 = mtile * 16 + g, r1 = r0 + 8;
        const int pix0 = br ? ((r0 / 7) * 112 + w * 7 + (r0 % 7)) : (w * LTOK + r0);
        const int pix1 = br ? ((r1 / 7) * 112 + w * 7 + (r1 % 7)) : (w * LTOK + r1);
        const int bro0 = (br ? (r0 % 7) : (r0 / 112)) * 7;
        const int bro1 = (br ? (r1 % 7) : (r1 / 112)) * 7;

        uint32_t qh[6], ql[6];
        #pragma unroll
        for (int p = 0; p < 3; p++) {
            int d = d0 + 8 * p;
            float a0v = qkv[(h * HDIM + d)     * HWPIX + pix0] * SCALE_F;
            float a1v = qkv[(h * HDIM + d + 1) * HWPIX + pix0] * SCALE_F;
            float b0v = qkv[(h * HDIM + d)     * HWPIX + pix1] * SCALE_F;
            float b1v = qkv[(h * HDIM + d + 1) * HWPIX + pix1] * SCALE_F;
            uint32_t hA = bfp(a0v, a1v), hB = bfp(b0v, b1v);
            qh[2 * p] = hA; qh[2 * p + 1] = hB;
            ql[2 * p]     = bfp(a0v - bflo(hA), a1v - bfhi(hA));
            ql[2 * p + 1] = bfp(b0v - bflo(hB), b1v - bfhi(hB));
        }

        float o[3][4];
        #pragma unroll
        for (int nd = 0; nd < 3; nd++)
            #pragma unroll
            for (int i = 0; i < 4; i++) o[nd][i] = 0.f;
        float rs0 = 0.f, rs1 = 0.f;

        for (int kt = 0; kt < NKT; kt++) {
            __syncthreads();
            #pragma unroll
            for (int i = 0; i < 6; i++) {
                int idx = tid + i * 224;
                int d = idx / KT, k = idx - d * KT;
                int m = kt * KT + k;
                int pix = br ? ((m / 7) * 112 + w * 7 + (m % 7)) : (w * LTOK + m);
                float kv = qkv[(192 + h * HDIM + d) * HWPIX + pix];
                float vv = qkv[(384 + h * HDIM + d) * HWPIX + pix];
                __nv_bfloat16 kh = __float2bfloat16(kv);
                __nv_bfloat16 vh = __float2bfloat16(vv);
                sKhi[k * KSTR + d] = __bfloat16_as_ushort(kh);
                sKlo[k * KSTR + d] = __bfloat16_as_ushort(__float2bfloat16(kv - __bfloat162float(kh)));
                sVhi[d * VSTR + k] = __bfloat16_as_ushort(vh);
                sVlo[d * VSTR + k] = __bfloat16_as_ushort(__float2bfloat16(vv - __bfloat162float(vh)));
            }
            __syncthreads();

            float bh0 = 0.f, bh1 = 0.f;
            if (!br) { bh0 = sb[bro0 + (kt >> 1)]; bh1 = sb[bro1 + (kt >> 1)]; }

            #pragma unroll
            for (int ks = 0; ks < 4; ks++) {
                const int nt0 = 2 * ks, nt1 = nt0 + 1;
                const bool has1 = (nt1 < 7);
                float sA[4] = {0.f, 0.f, 0.f, 0.f};
                float sB[4] = {0.f, 0.f, 0.f, 0.f};

                {
                    int kb = (nt0 * 8 + g) * KSTR + d0;
                    uint32_t kh00 = *(const uint32_t*)&sKhi[kb];
                    uint32_t kh01 = *(const uint32_t*)&sKhi[kb + 8];
                    uint32_t kh10 = *(const uint32_t*)&sKhi[kb + 16];
                    uint32_t kh11 = *(const uint32_t*)&sKhi[kb + 24];
                    uint32_t kl00 = *(const uint32_t*)&sKlo[kb];
                    uint32_t kl01 = *(const uint32_t*)&sKlo[kb + 8];
                    uint32_t kl10 = *(const uint32_t*)&sKlo[kb + 16];
                    uint32_t kl11 = *(const uint32_t*)&sKlo[kb + 24];
                    mma_bf16(sA, qh[0], qh[1], qh[2], qh[3], kh00, kh01);
                    mma_bf16(sA, ql[0], ql[1], ql[2], ql[3], kh00, kh01);
                    mma_bf16(sA, qh[0], qh[1], qh[2], qh[3], kl00, kl01);
                    mma_bf16(sA, qh[4], qh[5], 0u, 0u, kh10, kh11);
                    mma_bf16(sA, ql[4], ql[5], 0u, 0u, kh10, kh11);
                    mma_bf16(sA, qh[4], qh[5], 0u, 0u, kl10, kl11);
                }
                if (has1) {
                    int kb = (nt1 * 8 + g) * KSTR + d0;
                    uint32_t kh00 = *(const uint32_t*)&sKhi[kb];
                    uint32_t kh01 = *(const uint32_t*)&sKhi[kb + 8];
                    uint32_t kh10 = *(const uint32_t*)&sKhi[kb + 16];
                    uint32_t kh11 = *(const uint32_t*)&sKhi[kb + 24];
                    uint32_t kl00 = *(const uint32_t*)&sKlo[kb];
                    uint32_t kl01 = *(const uint32_t*)&sKlo[kb + 8];
                    uint32_t kl10 = *(const uint32_t*)&sKlo[kb + 16];
                    uint32_t kl11 = *(const uint32_t*)&sKlo[kb + 24];
                    mma_bf16(sB, qh[0], qh[1], qh[2], qh[3], kh00, kh01);
                    mma_bf16(sB, ql[0], ql[1], ql[2], ql[3], kh00, kh01);
                    mma_bf16(sB, qh[0], qh[1], qh[2], qh[3], kl00, kl01);
                    mma_bf16(sB, qh[4], qh[5], 0u, 0u, kh10, kh11);
                    mma_bf16(sB, ql[4], ql[5], 0u, 0u, kh10, kh11);
                    mma_bf16(sB, qh[4], qh[5], 0u, 0u, kl10, kl11);
                }

                float eA0, eA1, eA2, eA3, eB0 = 0.f, eB1 = 0.f, eB2 = 0.f, eB3 = 0.f;
                if (!br) {
                    eA0 = __expf(sA[0] + bh0); eA1 = __expf(sA[1] + bh0);
                    eA2 = __expf(sA[2] + bh1); eA3 = __expf(sA[3] + bh1);
                    if (has1) {
                        eB0 = __expf(sB[0] + bh0); eB1 = __expf(sB[1] + bh0);
                        eB2 = __expf(sB[2] + bh1); eB3 = __expf(sB[3] + bh1);
                    }
                } else {
                    int i0 = (nt0 + d0) % 7;
                    int i1 = i0 + 1; if (i1 == 7) i1 = 0;
                    int j1 = i1 + 1; if (j1 == 7) j1 = 0;
                    eA0 = __expf(sA[0] + sb[bro0 + i0]); eA1 = __expf(sA[1] + sb[bro0 + i1]);
                    eA2 = __expf(sA[2] + sb[bro1 + i0]); eA3 = __expf(sA[3] + sb[bro1 + i1]);
                    if (has1) {
                        eB0 = __expf(sB[0] + sb[bro0 + i1]); eB1 = __expf(sB[1] + sb[bro0 + j1]);
                        eB2 = __expf(sB[2] + sb[bro1 + i1]); eB3 = __expf(sB[3] + sb[bro1 + j1]);
                    }
                }
                rs0 += eA0 + eA1 + eB0 + eB1;
                rs1 += eA2 + eA3 + eB2 + eB3;

                uint32_t pa0 = bfp(eA0, eA1), pa1 = bfp(eA2, eA3);
                uint32_t pa2 = has1 ? bfp(eB0, eB1) : 0u;
                uint32_t pa3 = has1 ? bfp(eB2, eB3) : 0u;
                uint32_t pl0 = bfp(eA0 - bflo(pa0), eA1 - bfhi(pa0));
                uint32_t pl1 = bfp(eA2 - bflo(pa1), eA3 - bfhi(pa1));
                uint32_t pl2 = has1 ? bfp(eB0 - bflo(pa2), eB1 - bfhi(pa2)) : 0u;
                uint32_t pl3 = has1 ? bfp(eB2 - bflo(pa3), eB3 - bfhi(pa3)) : 0u;

                #pragma unroll
                for (int nd = 0; nd < 3; nd++) {
                    int vb = (nd * 8 + g) * VSTR + ks * 16 + d0;
                    uint32_t vh0 = *(const uint32_t*)&sVhi[vb];
                    uint32_t vh1 = *(const uint32_t*)&sVhi[vb + 8];
                    uint32_t vl0 = *(const uint32_t*)&sVlo[vb];
                    uint32_t vl1 = *(const uint32_t*)&sVlo[vb + 8];
                    mma_bf16(o[nd], pa0, pa1, pa2, pa3, vh0, vh1);
                    mma_bf16(o[nd], pl0, pl1, pl2, pl3, vh0, vh1);
                    mma_bf16(o[nd], pa0, pa1, pa2, pa3, vl0, vl1);
                }
            }
        }

        rs0 += __shfl_xor_sync(0xFFFFFFFFu, rs0, 1);
        rs0 += __shfl_xor_sync(0xFFFFFFFFu, rs0, 2);
        rs1 += __shfl_xor_sync(0xFFFFFFFFu, rs1, 1);
        rs1 += __shfl_xor_sync(0xFFFFFFFFu, rs1, 2);
        float inv0 = 1.f / rs0, inv1 = 1.f / rs1;
        #pragma unroll
        for (int nd = 0; nd < 3; nd++) {
            int d = nd * 8 + d0;
            outp[(h * HDIM + d)     * HWPIX + pix0] = o[nd][0] * inv0;
            outp[(h * HDIM + d + 1) * HWPIX + pix0] = o[nd][1] * inv0;
            outp[(h * HDIM + d)     * HWPIX + pix1] = o[nd][2] * inv1;
            outp[(h * HDIM + d + 1) * HWPIX + pix1] = o[nd][3] * inv1;
        }
    }
}

// ---------------- fused dual LePE -> 0.5*(h+v) -> bf16 hi/lo planes ----------------
__global__ __launch_bounds__(256) void lepe_fused(
    const float* __restrict__ attH, const float* __restrict__ attV,
    const float* __restrict__ wH, const float* __restrict__ bH,
    const float* __restrict__ wV, const float* __restrict__ bV,
    ushort_t* __restrict__ phi, ushort_t* __restrict__ plo)
{
    int t = blockIdx.x * blockDim.x + threadIdx.x;
    if (t >= Cdim * (HWPIX / 4)) return;
    int c = t / (HWPIX / 4);
    int r = t % (HWPIX / 4);
    int y = r / 28, x4 = (r % 28) * 4;
    const float* baseH = attH + c * HWPIX;
    const float* baseV = attV + c * HWPIX;

    float wvh[9], wvv[9];
    #pragma unroll
    for (int i = 0; i < 9; i++) { wvh[i] = wH[c * 9 + i]; wvv[i] = wV[c * 9 + i]; }
    float ah0 = bH[c], ah1 = ah0, ah2 = ah0, ah3 = ah0;
    float av0 = bV[c], av1 = av0, av2 = av0, av3 = av0;

    #pragma unroll
    for (int ky = 0; ky < 3; ky++) {
        int yy = y + ky - 1;
        if (yy < 0 || yy >= 112) continue;
        const float* rpH = baseH + yy * 112 + x4;
        const float* rpV = baseV + yy * 112 + x4;
        float4 mH = *(const float4*)rpH;
        float4 mV = *(const float4*)rpV;
        float lfH = (x4 > 0)   ? rpH[-1] : 0.f;
        float rtH = (x4 < 108) ? rpH[4]  : 0.f;
        float lfV = (x4 > 0)   ? rpV[-1] : 0.f;
        float rtV = (x4 < 108) ? rpV[4]  : 0.f;
        float h0 = wvh[ky*3], h1 = wvh[ky*3+1], h2 = wvh[ky*3+2];
        float v0 = wvv[ky*3], v1 = wvv[ky*3+1], v2 = wvv[ky*3+2];
        ah0 += h0 * lfH  + h1 * mH.x + h2 * mH.y;
        ah1 += h0 * mH.x + h1 * mH.y + h2 * mH.z;
        ah2 += h0 * mH.y + h1 * mH.z + h2 * mH.w;
        ah3 += h0 * mH.z + h1 * mH.w + h2 * rtH;
        av0 += v0 * lfV  + v1 * mV.x + v2 * mV.y;
        av1 += v0 * mV.x + v1 * mV.y + v2 * mV.z;
        av2 += v0 * mV.y + v1 * mV.z + v2 * mV.w;
        av3 += v0 * mV.z + v1 * mV.w + v2 * rtV;
    }

    float4 inH = *(const float4*)(baseH + y * 112 + x4);
    float4 inV = *(const float4*)(baseV + y * 112 + x4);
    const float RS2 = 0.70710678118654752f;
    float oh0 = inH.x + 0.5f * ah0 * (1.f + erff(ah0 * RS2));
    float oh1 = inH.y + 0.5f * ah1 * (1.f + erff(ah1 * RS2));
    float oh2 = inH.z + 0.5f * ah2 * (1.f + erff(ah2 * RS2));
    float oh3 = inH.w + 0.5f * ah3 * (1.f + erff(ah3 * RS2));
    float ov0 = inV.x + 0.5f * av0 * (1.f + erff(av0 * RS2));
    float ov1 = inV.y + 0.5f * av1 * (1.f + erff(av1 * RS2));
    float ov2 = inV.z + 0.5f * av2 * (1.f + erff(av2 * RS2));
    float ov3 = inV.w + 0.5f * av3 * (1.f + erff(av3 * RS2));

    float p0 = 0.5f * (oh0 + ov0);
    float p1 = 0.5f * (oh1 + ov1);
    float p2 = 0.5f * (oh2 + ov2);
    float p3 = 0.5f * (oh3 + ov3);

    uint32_t h0w = bfp(p0, p1), h1w = bfp(p2, p3);
    uint32_t l0w = bfp(p0 - bflo(h0w), p1 - bfhi(h0w));
    uint32_t l1w = bfp(p2 - bflo(h1w), p3 - bfhi(h1w));
    int idx = c * HWPIX + y * 112 + x4;
    *(uint2*)&phi[idx] = make_uint2(h0w, h1w);
    *(uint2*)&plo[idx] = make_uint2(l0w, l1w);
}

// ---------------- launch ----------------
extern "C" void kernel_launch(void* const* d_in, const int* in_sizes, int n_in,
                              void* d_out, int out_size)
{
    const float* x        = (const float*)d_in[0];
    const float* qkv_h_w  = (const float*)d_in[1];
    const float* qkv_h_b  = (const float*)d_in[2];
    const float* qkv_v_w  = (const float*)d_in[3];
    const float* qkv_v_b  = (const float*)d_in[4];
    const float* proj_w   = (const float*)d_in[5];
    const float* proj_b   = (const float*)d_in[6];
    const float* lepe_h_w = (const float*)d_in[7];
    const float* lepe_h_b = (const float*)d_in[8];
    const float* lepe_v_w = (const float*)d_in[9];
    const float* lepe_v_b = (const float*)d_in[10];
    const float* tab_h    = (const float*)d_in[11];
    const float* tab_v    = (const float*)d_in[12];
    float* out = (float*)d_out;

    float *qh, *qv, *ah, *av;
    ushort_t *xhi, *xlo, *phi, *plo, *whh, *whl, *wvh, *wvl, *pwh, *pwl;
    cudaGetSymbolAddress((void**)&qh, g_qkv_h);
    cudaGetSymbolAddress((void**)&qv, g_qkv_v);
    cudaGetSymbolAddress((void**)&ah, g_att_h);
    cudaGetSymbolAddress((void**)&av, g_att_v);
    cudaGetSymbolAddress((void**)&xhi, g_xhi);
    cudaGetSymbolAddress((void**)&xlo, g_xlo);
    cudaGetSymbolAddress((void**)&phi, g_phi);
    cudaGetSymbolAddress((void**)&plo, g_plo);
    cudaGetSymbolAddress((void**)&whh, g_whh);
    cudaGetSymbolAddress((void**)&whl, g_whl);
    cudaGetSymbolAddress((void**)&wvh, g_wvh);
    cudaGetSymbolAddress((void**)&wvl, g_wvl);
    cudaGetSymbolAddress((void**)&pwh, g_pwh);
    cudaGetSymbolAddress((void**)&pwl, g_pwl);

    // split inputs to bf16 hi/lo planes
    int nx4 = GK * NPIX / 4;
    split_kernel<<<(nx4 + 255) / 256, 256>>>((const float4*)x, (uint2*)xhi, (uint2*)xlo, nx4);
    int nw4 = M_QKV * GK / 4;
    split_kernel<<<(nw4 + 255) / 256, 256>>>((const float4*)qkv_h_w, (uint2*)whh, (uint2*)whl, nw4);
    split_kernel<<<(nw4 + 255) / 256, 256>>>((const float4*)qkv_v_w, (uint2*)wvh, (uint2*)wvl, nw4);
    int np4 = M_PROJ * GK / 4;
    split_kernel<<<(np4 + 255) / 256, 256>>>((const float4*)proj_w, (uint2*)pwh, (uint2*)pwl, np4);

    // QKV GEMMs (tensor core)
    dim3 gq(NPIX / 128, M_QKV / 64);
    gemm_mma<<<gq, 256>>>(whh, whl, xhi, xlo, qkv_h_b, qh);
    gemm_mma<<<gq, 256>>>(wvh, wvl, xhi, xlo, qkv_v_b, qv);

    // attention
    dim3 ga(16, NHEAD, 2);
    attn_mma<<<ga, 224>>>(tab_h, tab_v);

    // fused dual LePE + average + split
    int nthr = Cdim * (HWPIX / 4);
    lepe_fused<<<(nthr + 255) / 256, 256>>>(ah, av, lepe_h_w, lepe_h_b,
                                            lepe_v_w, lepe_v_b, phi, plo);

    // projection GEMM (tensor core)
    dim3 gp(NPIX / 128, M_PROJ / 64);
    gemm_mma<<<gp, 256>>>(pwh, pwl, phi, plo, proj_b, out);
}

// round 7
// speedup vs baseline: 2.3766x; 1.2587x over previous
#include <cuda_runtime.h>
#include <cuda_bf16.h>
#include <cstdint>
#include <math.h>

#define Cdim   192
#define NHEAD  8
#define HDIM   24
#define HWPIX  12544          // 112*112
#define LTOK   784            // 7*112
#define GK     192            // gemm K
#define NPIX   12544
#define M_QKV  576
#define M_PROJ 192
#define SCALE_F 0.20412414523193154f  // 24^-0.5

typedef unsigned short ushort_t;

// ---------------- scratch (device globals; no allocation) ----------------
__device__ float g_qkv_h[M_QKV * HWPIX];
__device__ float g_qkv_v[M_QKV * HWPIX];
__device__ float g_att_h[Cdim * HWPIX];
__device__ float g_att_v[Cdim * HWPIX];
__device__ ushort_t g_xhi[GK * NPIX];
__device__ ushort_t g_xlo[GK * NPIX];
__device__ ushort_t g_phi[GK * NPIX];
__device__ ushort_t g_plo[GK * NPIX];
__device__ ushort_t g_whh[M_QKV * GK];
__device__ ushort_t g_whl[M_QKV * GK];
__device__ ushort_t g_wvh[M_QKV * GK];
__device__ ushort_t g_wvl[M_QKV * GK];
__device__ ushort_t g_pwh[M_PROJ * GK];
__device__ ushort_t g_pwl[M_PROJ * GK];

// ---------------- bf16 helpers ----------------
__device__ __forceinline__ uint32_t bfp(float lo_el, float hi_el) {
    uint32_t r;
    asm("cvt.rn.bf16x2.f32 %0, %1, %2;" : "=r"(r) : "f"(hi_el), "f"(lo_el));
    return r;
}
__device__ __forceinline__ float bflo(uint32_t p) { return __uint_as_float(p << 16); }
__device__ __forceinline__ float bfhi(uint32_t p) { return __uint_as_float(p & 0xFFFF0000u); }

__device__ __forceinline__ uint32_t s2u(const void* p) {
    uint32_t a;
    asm("{ .reg .u64 t; cvta.to.shared.u64 t, %1; cvt.u32.u64 %0, t; }" : "=r"(a) : "l"(p));
    return a;
}

__device__ __forceinline__ void mma_bf16(float* c,
    uint32_t a0, uint32_t a1, uint32_t a2, uint32_t a3,
    uint32_t b0, uint32_t b1)
{
    asm volatile("mma.sync.aligned.m16n8k16.row.col.f32.bf16.bf16.f32 "
        "{%0,%1,%2,%3}, {%4,%5,%6,%7}, {%8,%9}, {%0,%1,%2,%3};"
        : "+f"(c[0]), "+f"(c[1]), "+f"(c[2]), "+f"(c[3])
        : "r"(a0), "r"(a1), "r"(a2), "r"(a3), "r"(b0), "r"(b1));
}

__device__ __forceinline__ void ldsm4t(uint32_t& r0, uint32_t& r1,
                                       uint32_t& r2, uint32_t& r3, uint32_t a)
{
    asm volatile("ldmatrix.sync.aligned.m8n8.x4.trans.shared.b16 {%0,%1,%2,%3}, [%4];"
        : "=r"(r0), "=r"(r1), "=r"(r2), "=r"(r3) : "r"(a));
}

#define CPA16(dst, src) asm volatile("cp.async.ca.shared.global [%0], [%1], 16;" :: "r"(dst), "l"(src) : "memory")
#define CPC()  asm volatile("cp.async.commit_group;" ::: "memory")
#define CPW1() asm volatile("cp.async.wait_group 1;" ::: "memory")
#define CPW0() asm volatile("cp.async.wait_group 0;" ::: "memory")

// ---------------- split fp32 -> bf16 hi/lo planes (vec4) ----------------
__global__ __launch_bounds__(256) void split_kernel(
    const float4* __restrict__ in, uint2* __restrict__ hi,
    uint2* __restrict__ lo, int n4)
{
    int i = blockIdx.x * blockDim.x + threadIdx.x;
    if (i >= n4) return;
    float4 v = in[i];
    uint32_t h0 = bfp(v.x, v.y);
    uint32_t h1 = bfp(v.z, v.w);
    uint32_t l0 = bfp(v.x - bflo(h0), v.y - bfhi(h0));
    uint32_t l1 = bfp(v.z - bflo(h1), v.w - bfhi(h1));
    hi[i] = make_uint2(h0, h1);
    lo[i] = make_uint2(l0, l1);
}

// combined weight split: 3 sources in one launch (segments by n4 counts)
__global__ __launch_bounds__(256) void split_weights(
    const float4* __restrict__ w1, uint2* __restrict__ h1p, uint2* __restrict__ l1p, int n1,
    const float4* __restrict__ w2, uint2* __restrict__ h2p, uint2* __restrict__ l2p, int n2,
    const float4* __restrict__ w3, uint2* __restrict__ h3p, uint2* __restrict__ l3p, int n3)
{
    int i = blockIdx.x * blockDim.x + threadIdx.x;
    const float4* src; uint2 *hd, *ld; int j = i;
    if (j < n1) { src = w1; hd = h1p; ld = l1p; }
    else if ((j -= n1) < n2) { src = w2; hd = h2p; ld = l2p; }
    else if ((j -= n2) < n3) { src = w3; hd = h3p; ld = l3p; }
    else return;
    float4 v = src[j];
    uint32_t h0 = bfp(v.x, v.y);
    uint32_t h1 = bfp(v.z, v.w);
    uint32_t l0 = bfp(v.x - bflo(h0), v.y - bfhi(h0));
    uint32_t l1 = bfp(v.z - bflo(h1), v.w - bfhi(h1));
    hd[j] = make_uint2(h0, h1);
    ld[j] = make_uint2(l0, l1);
}

// ---------------- hi/lo bf16 mma GEMM with cp.async double buffer ----------------
__global__ __launch_bounds__(256) void gemm_mma(
    const ushort_t* __restrict__ Ahi, const ushort_t* __restrict__ Alo,
    const ushort_t* __restrict__ Bhi, const ushort_t* __restrict__ Blo,
    const float* __restrict__ bias, float* __restrict__ C)
{
    __shared__ __align__(16) ushort_t sBh[2][32][136];
    __shared__ __align__(16) ushort_t sBl[2][32][136];
    const int tid = threadIdx.x;
    const int bn = blockIdx.x * 128, bm = blockIdx.y * 64;
    const int wid = tid >> 5, lane = tid & 31;
    const int wm = wid & 3, wn = wid >> 2;
    const int g = lane >> 2, q = lane & 3;
    const int wc = wn * 64;
    const int row0 = bm + wm * 16 + g;
    const int row1 = row0 + 8;

    float acc[8][4];
    #pragma unroll
    for (int i = 0; i < 8; i++)
        #pragma unroll
        for (int j = 0; j < 4; j++) acc[i][j] = 0.f;

    const int rB = tid >> 3;
    const int cB = (tid & 7) * 8;

    uint32_t dsth[2], dstl[2];
    dsth[0] = s2u(&sBh[0][rB][cB]); dsth[1] = s2u(&sBh[1][rB][cB]);
    dstl[0] = s2u(&sBl[0][rB][cB]); dstl[1] = s2u(&sBl[1][rB][cB]);

    const int lm = lane >> 3, lr = lane & 7;
    const int lkrow = (lm & 1) * 8 + lr;
    const int lncol = wc + (lm >> 1) * 8;
    uint32_t sbh_base[2], sbl_base[2];
    sbh_base[0] = s2u(&sBh[0][lkrow][lncol]); sbh_base[1] = s2u(&sBh[1][lkrow][lncol]);
    sbl_base[0] = s2u(&sBl[0][lkrow][lncol]); sbl_base[1] = s2u(&sBl[1][lkrow][lncol]);

    // prologue: issue tile 0
    {
        const ushort_t* bh = &Bhi[rB * NPIX + bn + cB];
        const ushort_t* bl = &Blo[rB * NPIX + bn + cB];
        CPA16(dsth[0], bh); CPA16(dsth[0] + 128, bh + 64);
        CPA16(dstl[0], bl); CPA16(dstl[0] + 128, bl + 64);
        CPC();
    }

    #pragma unroll
    for (int ki = 0; ki < 6; ki++) {
        if (ki < 5) {
            const int kn = (ki + 1) * 32;
            const int bf = (ki + 1) & 1;
            const ushort_t* bh = &Bhi[(kn + rB) * NPIX + bn + cB];
            const ushort_t* bl = &Blo[(kn + rB) * NPIX + bn + cB];
            CPA16(dsth[bf], bh); CPA16(dsth[bf] + 128, bh + 64);
            CPA16(dstl[bf], bl); CPA16(dstl[bf] + 128, bl + 64);
            CPC();
            CPW1();
        } else {
            CPW0();
        }
        __syncthreads();

        const int buf = ki & 1;
        const int k0 = ki * 32;
        #pragma unroll
        for (int hh = 0; hh < 2; hh++) {
            const int kk = k0 + hh * 16;
            uint32_t ah[4], al[4];
            ah[0] = *(const uint32_t*)&Ahi[row0 * GK + kk + 2 * q];
            ah[1] = *(const uint32_t*)&Ahi[row1 * GK + kk + 2 * q];
            ah[2] = *(const uint32_t*)&Ahi[row0 * GK + kk + 2 * q + 8];
            ah[3] = *(const uint32_t*)&Ahi[row1 * GK + kk + 2 * q + 8];
            al[0] = *(const uint32_t*)&Alo[row0 * GK + kk + 2 * q];
            al[1] = *(const uint32_t*)&Alo[row1 * GK + kk + 2 * q];
            al[2] = *(const uint32_t*)&Alo[row0 * GK + kk + 2 * q + 8];
            al[3] = *(const uint32_t*)&Alo[row1 * GK + kk + 2 * q + 8];

            const uint32_t hoff = (uint32_t)(hh * 16 * 136) * 2;
            #pragma unroll
            for (int j = 0; j < 4; j++) {
                uint32_t off = hoff + (uint32_t)(j * 16) * 2;
                uint32_t bh0, bh1, bh2, bh3, bl0, bl1, bl2, bl3;
                ldsm4t(bh0, bh1, bh2, bh3, sbh_base[buf] + off);
                ldsm4t(bl0, bl1, bl2, bl3, sbl_base[buf] + off);
                float* c0 = acc[2 * j];
                float* c1 = acc[2 * j + 1];
                mma_bf16(c0, ah[0], ah[1], ah[2], ah[3], bh0, bh1);
                mma_bf16(c0, al[0], al[1], al[2], al[3], bh0, bh1);
                mma_bf16(c0, ah[0], ah[1], ah[2], ah[3], bl0, bl1);
                mma_bf16(c1, ah[0], ah[1], ah[2], ah[3], bh2, bh3);
                mma_bf16(c1, al[0], al[1], al[2], al[3], bh2, bh3);
                mma_bf16(c1, ah[0], ah[1], ah[2], ah[3], bl2, bl3);
            }
        }
        __syncthreads();
    }

    const float b0 = bias[row0], b1 = bias[row1];
    #pragma unroll
    for (int nf = 0; nf < 8; nf++) {
        int col = bn + wc + nf * 8 + 2 * q;
        *(float2*)&C[row0 * NPIX + col] = make_float2(acc[nf][0] + b0, acc[nf][1] + b0);
        *(float2*)&C[row1 * NPIX + col] = make_float2(acc[nf][2] + b1, acc[nf][3] + b1);
    }
}

// ============================================================================
// mma.sync bf16 flash attention — full K/V resident in SMEM (fill once)
// ============================================================================
#define KSTR 36        // K row stride (halves)
#define VSTRF 792      // V dim-row stride (halves): 784 keys + 8 pad
#define NW    14       // warps

// SMEM byte offsets
#define A_SKH 0
#define A_SKL (A_SKH + LTOK * KSTR * 2)          // 56448
#define A_SVH (A_SKL + LTOK * KSTR * 2)          // 112896
#define A_SVL (A_SVH + HDIM * VSTRF * 2)         // 150912
#define A_SB  (A_SVL + HDIM * VSTRF * 2)         // 188928
#define A_TOTAL (A_SB + 256)

__global__ __launch_bounds__(448, 1) void attn_mma(
    const float* __restrict__ tab_h, const float* __restrict__ tab_v)
{
    extern __shared__ char asm_[];
    ushort_t* sKhi = (ushort_t*)(asm_ + A_SKH);
    ushort_t* sKlo = (ushort_t*)(asm_ + A_SKL);
    ushort_t* sVhi = (ushort_t*)(asm_ + A_SVH);
    ushort_t* sVlo = (ushort_t*)(asm_ + A_SVL);
    float* sb = (float*)(asm_ + A_SB);

    const int tid = threadIdx.x;
    const int w = blockIdx.x, h = blockIdx.y, br = blockIdx.z;
    const float* __restrict__ qkv = br ? g_qkv_v : g_qkv_h;
    float* __restrict__ outp = br ? g_att_v : g_att_h;
    const float* __restrict__ tab = br ? tab_v : tab_h;

    if (tid < 49) {
        int r1 = tid / 7, r2 = tid % 7, off = r1 - r2 + 6;
        sb[tid] = br ? tab[(6 * 13 + off) * NHEAD + h]
                     : tab[(off * 13 + 6) * NHEAD + h];
    }
    // zero pad regions only: K dims 24..35 (784*12), V keys 784..791 (24*8)
    for (int i = tid; i < LTOK * 12; i += 448) {
        int k = i / 12, d = 24 + (i % 12);
        sKhi[k * KSTR + d] = 0; sKlo[k * KSTR + d] = 0;
    }
    if (tid < HDIM * 8) {
        int d = tid / 8, k = LTOK + (tid % 8);
        sVhi[d * VSTRF + k] = 0; sVlo[d * VSTRF + k] = 0;
    }
    // fill K/V once (hi/lo split)
    for (int idx = tid; idx < LTOK * HDIM; idx += 448) {
        int d = idx / LTOK, k = idx - d * LTOK;
        int pix = br ? ((k / 7) * 112 + w * 7 + (k % 7)) : (w * LTOK + k);
        float kv = qkv[(192 + h * HDIM + d) * HWPIX + pix];
        float vv = qkv[(384 + h * HDIM + d) * HWPIX + pix];
        __nv_bfloat16 kh = __float2bfloat16(kv);
        __nv_bfloat16 vh = __float2bfloat16(vv);
        sKhi[k * KSTR + d] = __bfloat16_as_ushort(kh);
        sKlo[k * KSTR + d] = __bfloat16_as_ushort(__float2bfloat16(kv - __bfloat162float(kh)));
        sVhi[d * VSTRF + k] = __bfloat16_as_ushort(vh);
        sVlo[d * VSTRF + k] = __bfloat16_as_ushort(__float2bfloat16(vv - __bfloat162float(vh)));
    }
    __syncthreads();

    const int warp = tid >> 5, lane = tid & 31;
    const int g = lane >> 2, q = lane & 3;
    const int d0 = 2 * q;

    for (int mt = warp; mt < 49; mt += NW) {
        const int r0 = mt * 16 + g, r1 = r0 + 8;
        const int pix0 = br ? ((r0 / 7) * 112 + w * 7 + (r0 % 7)) : (w * LTOK + r0);
        const int pix1 = br ? ((r1 / 7) * 112 + w * 7 + (r1 % 7)) : (w * LTOK + r1);
        const int bro0 = (br ? (r0 % 7) : (r0 / 112)) * 7;
        const int bro1 = (br ? (r1 % 7) : (r1 / 112)) * 7;

        uint32_t qh[6], ql[6];
        #pragma unroll
        for (int p = 0; p < 3; p++) {
            int d = d0 + 8 * p;
            float a0v = qkv[(h * HDIM + d)     * HWPIX + pix0] * SCALE_F;
            float a1v = qkv[(h * HDIM + d + 1) * HWPIX + pix0] * SCALE_F;
            float b0v = qkv[(h * HDIM + d)     * HWPIX + pix1] * SCALE_F;
            float b1v = qkv[(h * HDIM + d + 1) * HWPIX + pix1] * SCALE_F;
            uint32_t hA = bfp(a0v, a1v), hB = bfp(b0v, b1v);
            qh[2 * p] = hA; qh[2 * p + 1] = hB;
            ql[2 * p]     = bfp(a0v - bflo(hA), a1v - bfhi(hA));
            ql[2 * p + 1] = bfp(b0v - bflo(hB), b1v - bfhi(hB));
        }

        float o[3][4];
        #pragma unroll
        for (int nd = 0; nd < 3; nd++)
            #pragma unroll
            for (int i = 0; i < 4; i++) o[nd][i] = 0.f;
        float rs0 = 0.f, rs1 = 0.f;

        for (int kt = 0; kt < 14; kt++) {
            float bh0 = 0.f, bh1 = 0.f;
            if (!br) { bh0 = sb[bro0 + (kt >> 1)]; bh1 = sb[bro1 + (kt >> 1)]; }
            const int kbase = kt * 56;

            #pragma unroll
            for (int ks = 0; ks < 4; ks++) {
                const int nt0 = 2 * ks, nt1 = nt0 + 1;
                const bool has1 = (nt1 < 7);
                float sA[4] = {0.f, 0.f, 0.f, 0.f};
                float sB[4] = {0.f, 0.f, 0.f, 0.f};

                {
                    int kb = (kbase + nt0 * 8 + g) * KSTR + d0;
                    uint32_t kh00 = *(const uint32_t*)&sKhi[kb];
                    uint32_t kh01 = *(const uint32_t*)&sKhi[kb + 8];
                    uint32_t kh10 = *(const uint32_t*)&sKhi[kb + 16];
                    uint32_t kh11 = *(const uint32_t*)&sKhi[kb + 24];
                    uint32_t kl00 = *(const uint32_t*)&sKlo[kb];
                    uint32_t kl01 = *(const uint32_t*)&sKlo[kb + 8];
                    uint32_t kl10 = *(const uint32_t*)&sKlo[kb + 16];
                    uint32_t kl11 = *(const uint32_t*)&sKlo[kb + 24];
                    mma_bf16(sA, qh[0], qh[1], qh[2], qh[3], kh00, kh01);
                    mma_bf16(sA, ql[0], ql[1], ql[2], ql[3], kh00, kh01);
                    mma_bf16(sA, qh[0], qh[1], qh[2], qh[3], kl00, kl01);
                    mma_bf16(sA, qh[4], qh[5], 0u, 0u, kh10, kh11);
                    mma_bf16(sA, ql[4], ql[5], 0u, 0u, kh10, kh11);
                    mma_bf16(sA, qh[4], qh[5], 0u, 0u, kl10, kl11);
                }
                if (has1) {
                    int kb = (kbase + nt1 * 8 + g) * KSTR + d0;
                    uint32_t kh00 = *(const uint32_t*)&sKhi[kb];
                    uint32_t kh01 = *(const uint32_t*)&sKhi[kb + 8];
                    uint32_t kh10 = *(const uint32_t*)&sKhi[kb + 16];
                    uint32_t kh11 = *(const uint32_t*)&sKhi[kb + 24];
                    uint32_t kl00 = *(const uint32_t*)&sKlo[kb];
                    uint32_t kl01 = *(const uint32_t*)&sKlo[kb + 8];
                    uint32_t kl10 = *(const uint32_t*)&sKlo[kb + 16];
                    uint32_t kl11 = *(const uint32_t*)&sKlo[kb + 24];
                    mma_bf16(sB, qh[0], qh[1], qh[2], qh[3], kh00, kh01);
                    mma_bf16(sB, ql[0], ql[1], ql[2], ql[3], kh00, kh01);
                    mma_bf16(sB, qh[0], qh[1], qh[2], qh[3], kl00, kl01);
                    mma_bf16(sB, qh[4], qh[5], 0u, 0u, kh10, kh11);
                    mma_bf16(sB, ql[4], ql[5], 0u, 0u, kh10, kh11);
                    mma_bf16(sB, qh[4], qh[5], 0u, 0u, kl10, kl11);
                }

                float eA0, eA1, eA2, eA3, eB0 = 0.f, eB1 = 0.f, eB2 = 0.f, eB3 = 0.f;
                if (!br) {
                    eA0 = __expf(sA[0] + bh0); eA1 = __expf(sA[1] + bh0);
                    eA2 = __expf(sA[2] + bh1); eA3 = __expf(sA[3] + bh1);
                    if (has1) {
                        eB0 = __expf(sB[0] + bh0); eB1 = __expf(sB[1] + bh0);
                        eB2 = __expf(sB[2] + bh1); eB3 = __expf(sB[3] + bh1);
                    }
                } else {
                    int i0 = (nt0 + d0) % 7;
                    int i1 = i0 + 1; if (i1 == 7) i1 = 0;
                    int j1 = i1 + 1; if (j1 == 7) j1 = 0;
                    eA0 = __expf(sA[0] + sb[bro0 + i0]); eA1 = __expf(sA[1] + sb[bro0 + i1]);
                    eA2 = __expf(sA[2] + sb[bro1 + i0]); eA3 = __expf(sA[3] + sb[bro1 + i1]);
                    if (has1) {
                        eB0 = __expf(sB[0] + sb[bro0 + i1]); eB1 = __expf(sB[1] + sb[bro0 + j1]);
                        eB2 = __expf(sB[2] + sb[bro1 + i1]); eB3 = __expf(sB[3] + sb[bro1 + j1]);
                    }
                }
                rs0 += eA0 + eA1 + eB0 + eB1;
                rs1 += eA2 + eA3 + eB2 + eB3;

                uint32_t pa0 = bfp(eA0, eA1), pa1 = bfp(eA2, eA3);
                uint32_t pa2 = has1 ? bfp(eB0, eB1) : 0u;
                uint32_t pa3 = has1 ? bfp(eB2, eB3) : 0u;
                uint32_t pl0 = bfp(eA0 - bflo(pa0), eA1 - bfhi(pa0));
                uint32_t pl1 = bfp(eA2 - bflo(pa1), eA3 - bfhi(pa1));
                uint32_t pl2 = has1 ? bfp(eB0 - bflo(pa2), eB1 - bfhi(pa2)) : 0u;
                uint32_t pl3 = has1 ? bfp(eB2 - bflo(pa3), eB3 - bfhi(pa3)) : 0u;

                #pragma unroll
                for (int nd = 0; nd < 3; nd++) {
                    int vb = (nd * 8 + g) * VSTRF + kbase + ks * 16 + d0;
                    uint32_t vh0 = *(const uint32_t*)&sVhi[vb];
                    uint32_t vh1 = *(const uint32_t*)&sVhi[vb + 8];
                    uint32_t vl0 = *(const uint32_t*)&sVlo[vb];
                    uint32_t vl1 = *(const uint32_t*)&sVlo[vb + 8];
                    mma_bf16(o[nd], pa0, pa1, pa2, pa3, vh0, vh1);
                    mma_bf16(o[nd], pl0, pl1, pl2, pl3, vh0, vh1);
                    mma_bf16(o[nd], pa0, pa1, pa2, pa3, vl0, vl1);
                }
            }
        }

        rs0 += __shfl_xor_sync(0xFFFFFFFFu, rs0, 1);
        rs0 += __shfl_xor_sync(0xFFFFFFFFu, rs0, 2);
        rs1 += __shfl_xor_sync(0xFFFFFFFFu, rs1, 1);
        rs1 += __shfl_xor_sync(0xFFFFFFFFu, rs1, 2);
        float inv0 = 1.f / rs0, inv1 = 1.f / rs1;
        #pragma unroll
        for (int nd = 0; nd < 3; nd++) {
            int d = nd * 8 + d0;
            outp[(h * HDIM + d)     * HWPIX + pix0] = o[nd][0] * inv0;
            outp[(h * HDIM + d + 1) * HWPIX + pix0] = o[nd][1] * inv0;
            outp[(h * HDIM + d)     * HWPIX + pix1] = o[nd][2] * inv1;
            outp[(h * HDIM + d + 1) * HWPIX + pix1] = o[nd][3] * inv1;
        }
    }
}

// ---------------- fused dual LePE -> 0.5*(h+v) -> bf16 hi/lo planes ----------------
__global__ __launch_bounds__(256) void lepe_fused(
    const float* __restrict__ attH, const float* __restrict__ attV,
    const float* __restrict__ wH, const float* __restrict__ bH,
    const float* __restrict__ wV, const float* __restrict__ bV,
    ushort_t* __restrict__ phi, ushort_t* __restrict__ plo)
{
    int t = blockIdx.x * blockDim.x + threadIdx.x;
    if (t >= Cdim * (HWPIX / 4)) return;
    int c = t / (HWPIX / 4);
    int r = t % (HWPIX / 4);
    int y = r / 28, x4 = (r % 28) * 4;
    const float* baseH = attH + c * HWPIX;
    const float* baseV = attV + c * HWPIX;

    float wvh[9], wvv[9];
    #pragma unroll
    for (int i = 0; i < 9; i++) { wvh[i] = wH[c * 9 + i]; wvv[i] = wV[c * 9 + i]; }
    float ah0 = bH[c], ah1 = ah0, ah2 = ah0, ah3 = ah0;
    float av0 = bV[c], av1 = av0, av2 = av0, av3 = av0;

    #pragma unroll
    for (int ky = 0; ky < 3; ky++) {
        int yy = y + ky - 1;
        if (yy < 0 || yy >= 112) continue;
        const float* rpH = baseH + yy * 112 + x4;
        const float* rpV = baseV + yy * 112 + x4;
        float4 mH = *(const float4*)rpH;
        float4 mV = *(const float4*)rpV;
        float lfH = (x4 > 0)   ? rpH[-1] : 0.f;
        float rtH = (x4 < 108) ? rpH[4]  : 0.f;
        float lfV = (x4 > 0)   ? rpV[-1] : 0.f;
        float rtV = (x4 < 108) ? rpV[4]  : 0.f;
        float h0 = wvh[ky*3], h1 = wvh[ky*3+1], h2 = wvh[ky*3+2];
        float v0 = wvv[ky*3], v1 = wvv[ky*3+1], v2 = wvv[ky*3+2];
        ah0 += h0 * lfH  + h1 * mH.x + h2 * mH.y;
        ah1 += h0 * mH.x + h1 * mH.y + h2 * mH.z;
        ah2 += h0 * mH.y + h1 * mH.z + h2 * mH.w;
        ah3 += h0 * mH.z + h1 * mH.w + h2 * rtH;
        av0 += v0 * lfV  + v1 * mV.x + v2 * mV.y;
        av1 += v0 * mV.x + v1 * mV.y + v2 * mV.z;
        av2 += v0 * mV.y + v1 * mV.z + v2 * mV.w;
        av3 += v0 * mV.z + v1 * mV.w + v2 * rtV;
    }

    float4 inH = *(const float4*)(baseH + y * 112 + x4);
    float4 inV = *(const float4*)(baseV + y * 112 + x4);
    const float RS2 = 0.70710678118654752f;
    float oh0 = inH.x + 0.5f * ah0 * (1.f + erff(ah0 * RS2));
    float oh1 = inH.y + 0.5f * ah1 * (1.f + erff(ah1 * RS2));
    float oh2 = inH.z + 0.5f * ah2 * (1.f + erff(ah2 * RS2));
    float oh3 = inH.w + 0.5f * ah3 * (1.f + erff(ah3 * RS2));
    float ov0 = inV.x + 0.5f * av0 * (1.f + erff(av0 * RS2));
    float ov1 = inV.y + 0.5f * av1 * (1.f + erff(av1 * RS2));
    float ov2 = inV.z + 0.5f * av2 * (1.f + erff(av2 * RS2));
    float ov3 = inV.w + 0.5f * av3 * (1.f + erff(av3 * RS2));

    float p0 = 0.5f * (oh0 + ov0);
    float p1 = 0.5f * (oh1 + ov1);
    float p2 = 0.5f * (oh2 + ov2);
    float p3 = 0.5f * (oh3 + ov3);

    uint32_t h0w = bfp(p0, p1), h1w = bfp(p2, p3);
    uint32_t l0w = bfp(p0 - bflo(h0w), p1 - bfhi(h0w));
    uint32_t l1w = bfp(p2 - bflo(h1w), p3 - bfhi(h1w));
    int idx = c * HWPIX + y * 112 + x4;
    *(uint2*)&phi[idx] = make_uint2(h0w, h1w);
    *(uint2*)&plo[idx] = make_uint2(l0w, l1w);
}

// ---------------- launch ----------------
extern "C" void kernel_launch(void* const* d_in, const int* in_sizes, int n_in,
                              void* d_out, int out_size)
{
    const float* x        = (const float*)d_in[0];
    const float* qkv_h_w  = (const float*)d_in[1];
    const float* qkv_h_b  = (const float*)d_in[2];
    const float* qkv_v_w  = (const float*)d_in[3];
    const float* qkv_v_b  = (const float*)d_in[4];
    const float* proj_w   = (const float*)d_in[5];
    const float* proj_b   = (const float*)d_in[6];
    const float* lepe_h_w = (const float*)d_in[7];
    const float* lepe_h_b = (const float*)d_in[8];
    const float* lepe_v_w = (const float*)d_in[9];
    const float* lepe_v_b = (const float*)d_in[10];
    const float* tab_h    = (const float*)d_in[11];
    const float* tab_v    = (const float*)d_in[12];
    float* out = (float*)d_out;

    float *qh, *qv, *ah, *av;
    ushort_t *xhi, *xlo, *phi, *plo, *whh, *whl, *wvh, *wvl, *pwh, *pwl;
    cudaGetSymbolAddress((void**)&qh, g_qkv_h);
    cudaGetSymbolAddress((void**)&qv, g_qkv_v);
    cudaGetSymbolAddress((void**)&ah, g_att_h);
    cudaGetSymbolAddress((void**)&av, g_att_v);
    cudaGetSymbolAddress((void**)&xhi, g_xhi);
    cudaGetSymbolAddress((void**)&xlo, g_xlo);
    cudaGetSymbolAddress((void**)&phi, g_phi);
    cudaGetSymbolAddress((void**)&plo, g_plo);
    cudaGetSymbolAddress((void**)&whh, g_whh);
    cudaGetSymbolAddress((void**)&whl, g_whl);
    cudaGetSymbolAddress((void**)&wvh, g_wvh);
    cudaGetSymbolAddress((void**)&wvl, g_wvl);
    cudaGetSymbolAddress((void**)&pwh, g_pwh);
    cudaGetSymbolAddress((void**)&pwl, g_pwl);

    // split x + all weights (2 launches total)
    int nx4 = GK * NPIX / 4;
    split_kernel<<<(nx4 + 255) / 256, 256>>>((const float4*)x, (uint2*)xhi, (uint2*)xlo, nx4);
    int nw4 = M_QKV * GK / 4;
    int np4 = M_PROJ * GK / 4;
    int ntotw = nw4 * 2 + np4;
    split_weights<<<(ntotw + 255) / 256, 256>>>(
        (const float4*)qkv_h_w, (uint2*)whh, (uint2*)whl, nw4,
        (const float4*)qkv_v_w, (uint2*)wvh, (uint2*)wvl, nw4,
        (const float4*)proj_w,  (uint2*)pwh, (uint2*)pwl, np4);

    // QKV GEMMs (tensor core, cp.async double-buffered)
    dim3 gq(NPIX / 128, M_QKV / 64);
    gemm_mma<<<gq, 256>>>(whh, whl, xhi, xlo, qkv_h_b, qh);
    gemm_mma<<<gq, 256>>>(wvh, wvl, xhi, xlo, qkv_v_b, qv);

    // attention (full K/V resident)
    cudaFuncSetAttribute(attn_mma,
                         cudaFuncAttributeMaxDynamicSharedMemorySize, A_TOTAL);
    dim3 ga(16, NHEAD, 2);
    attn_mma<<<ga, 448, A_TOTAL>>>(tab_h, tab_v);

    // fused dual LePE + average + split
    int nthr = Cdim * (HWPIX / 4);
    lepe_fused<<<(nthr + 255) / 256, 256>>>(ah, av, lepe_h_w, lepe_h_b,
                                            lepe_v_w, lepe_v_b, phi, plo);

    // projection GEMM (tensor core)
    dim3 gp(NPIX / 128, M_PROJ / 64);
    gemm_mma<<<gp, 256>>>(pwh, pwl, phi, plo, proj_b, out);
}

// round 8
// speedup vs baseline: 2.5443x; 1.0706x over previous
#include <cuda_runtime.h>
#include <cuda_bf16.h>
#include <cstdint>
#include <math.h>

#define Cdim   192
#define NHEAD  8
#define HDIM   24
#define HWPIX  12544          // 112*112
#define LTOK   784            // 7*112
#define GK     192            // gemm K
#define NPIX   12544
#define M_QKV  576
#define M_PROJ 192
#define SCALE_F 0.20412414523193154f  // 24^-0.5

typedef unsigned short ushort_t;

// ---------------- scratch (device globals; no allocation) ----------------
__device__ float g_qkv_h[M_QKV * HWPIX];
__device__ float g_qkv_v[M_QKV * HWPIX];
__device__ float g_att_h[Cdim * HWPIX];
__device__ float g_att_v[Cdim * HWPIX];
__device__ ushort_t g_xhi[GK * NPIX];
__device__ ushort_t g_xlo[GK * NPIX];
__device__ ushort_t g_phi[GK * NPIX];
__device__ ushort_t g_plo[GK * NPIX];
__device__ ushort_t g_whh[M_QKV * GK];
__device__ ushort_t g_whl[M_QKV * GK];
__device__ ushort_t g_wvh[M_QKV * GK];
__device__ ushort_t g_wvl[M_QKV * GK];
__device__ ushort_t g_pwh[M_PROJ * GK];
__device__ ushort_t g_pwl[M_PROJ * GK];

// ---------------- bf16 helpers ----------------
__device__ __forceinline__ uint32_t bfp(float lo_el, float hi_el) {
    uint32_t r;
    asm("cvt.rn.bf16x2.f32 %0, %1, %2;" : "=r"(r) : "f"(hi_el), "f"(lo_el));
    return r;
}
__device__ __forceinline__ float bflo(uint32_t p) { return __uint_as_float(p << 16); }
__device__ __forceinline__ float bfhi(uint32_t p) { return __uint_as_float(p & 0xFFFF0000u); }

__device__ __forceinline__ uint32_t s2u(const void* p) {
    uint32_t a;
    asm("{ .reg .u64 t; cvta.to.shared.u64 t, %1; cvt.u32.u64 %0, t; }" : "=r"(a) : "l"(p));
    return a;
}

__device__ __forceinline__ void mma_bf16(float* c,
    uint32_t a0, uint32_t a1, uint32_t a2, uint32_t a3,
    uint32_t b0, uint32_t b1)
{
    asm volatile("mma.sync.aligned.m16n8k16.row.col.f32.bf16.bf16.f32 "
        "{%0,%1,%2,%3}, {%4,%5,%6,%7}, {%8,%9}, {%0,%1,%2,%3};"
        : "+f"(c[0]), "+f"(c[1]), "+f"(c[2]), "+f"(c[3])
        : "r"(a0), "r"(a1), "r"(a2), "r"(a3), "r"(b0), "r"(b1));
}

__device__ __forceinline__ void ldsm4t(uint32_t& r0, uint32_t& r1,
                                       uint32_t& r2, uint32_t& r3, uint32_t a)
{
    asm volatile("ldmatrix.sync.aligned.m8n8.x4.trans.shared.b16 {%0,%1,%2,%3}, [%4];"
        : "=r"(r0), "=r"(r1), "=r"(r2), "=r"(r3) : "r"(a));
}
__device__ __forceinline__ void ldsm4(uint32_t& r0, uint32_t& r1,
                                      uint32_t& r2, uint32_t& r3, uint32_t a)
{
    asm volatile("ldmatrix.sync.aligned.m8n8.x4.shared.b16 {%0,%1,%2,%3}, [%4];"
        : "=r"(r0), "=r"(r1), "=r"(r2), "=r"(r3) : "r"(a));
}

#define CPA16(dst, src) asm volatile("cp.async.ca.shared.global [%0], [%1], 16;" :: "r"(dst), "l"(src) : "memory")
#define CPC()  asm volatile("cp.async.commit_group;" ::: "memory")
#define CPW1() asm volatile("cp.async.wait_group 1;" ::: "memory")
#define CPW0() asm volatile("cp.async.wait_group 0;" ::: "memory")

// ---------------- split fp32 -> bf16 hi/lo planes (vec4) ----------------
__global__ __launch_bounds__(256) void split_kernel(
    const float4* __restrict__ in, uint2* __restrict__ hi,
    uint2* __restrict__ lo, int n4)
{
    int i = blockIdx.x * blockDim.x + threadIdx.x;
    if (i >= n4) return;
    float4 v = in[i];
    uint32_t h0 = bfp(v.x, v.y);
    uint32_t h1 = bfp(v.z, v.w);
    uint32_t l0 = bfp(v.x - bflo(h0), v.y - bfhi(h0));
    uint32_t l1 = bfp(v.z - bflo(h1), v.w - bfhi(h1));
    hi[i] = make_uint2(h0, h1);
    lo[i] = make_uint2(l0, l1);
}

__global__ __launch_bounds__(256) void split_weights(
    const float4* __restrict__ w1, uint2* __restrict__ h1p, uint2* __restrict__ l1p, int n1,
    const float4* __restrict__ w2, uint2* __restrict__ h2p, uint2* __restrict__ l2p, int n2,
    const float4* __restrict__ w3, uint2* __restrict__ h3p, uint2* __restrict__ l3p, int n3)
{
    int i = blockIdx.x * blockDim.x + threadIdx.x;
    const float4* src; uint2 *hd, *ld; int j = i;
    if (j < n1) { src = w1; hd = h1p; ld = l1p; }
    else if ((j -= n1) < n2) { src = w2; hd = h2p; ld = l2p; }
    else if ((j -= n2) < n3) { src = w3; hd = h3p; ld = l3p; }
    else return;
    float4 v = src[j];
    uint32_t h0 = bfp(v.x, v.y);
    uint32_t h1 = bfp(v.z, v.w);
    uint32_t l0 = bfp(v.x - bflo(h0), v.y - bfhi(h0));
    uint32_t l1 = bfp(v.z - bflo(h1), v.w - bfhi(h1));
    hd[j] = make_uint2(h0, h1);
    ld[j] = make_uint2(l0, l1);
}

// ---------------- hi/lo bf16 mma GEMM, A staged + ldmatrix, cp.async DB ------------
// dynamic smem layout (halves):
//   sBh[2][32][136]  @ 0
//   sBl[2][32][136]  @ 8704
//   sAh[2][64][40]   @ 17408
//   sAl[2][64][40]   @ 22528
// total 27648 halves = 55296 bytes
#define G_SBH 0
#define G_SBL 8704
#define G_SAH 17408
#define G_SAL 22528
#define G_BSTR 136
#define G_BBUF 4352
#define G_ASTR 40
#define G_ABUF 2560
#define G_TOTAL_BYTES 55296

__global__ __launch_bounds__(256) void gemm_mma(
    const ushort_t* __restrict__ Ahi, const ushort_t* __restrict__ Alo,
    const ushort_t* __restrict__ Bhi, const ushort_t* __restrict__ Blo,
    const float* __restrict__ bias, float* __restrict__ C)
{
    extern __shared__ ushort_t gsm[];
    const int tid = threadIdx.x;
    const int bn = blockIdx.x * 128, bm = blockIdx.y * 64;
    const int wid = tid >> 5, lane = tid & 31;
    const int wm = wid & 3, wn = wid >> 2;
    const int g = lane >> 2, q = lane & 3;
    const int wc = wn * 64;
    const int row0 = bm + wm * 16 + g;
    const int row1 = row0 + 8;

    float acc[8][4];
    #pragma unroll
    for (int i = 0; i < 8; i++)
        #pragma unroll
        for (int j = 0; j < 4; j++) acc[i][j] = 0.f;

    // B staging: 32 rows x 128 cols
    const int rB = tid >> 3;
    const int cB = (tid & 7) * 8;
    // A staging: 64 rows x 32 halves
    const int rA = tid >> 2;
    const int cA = (tid & 3) * 8;

    uint32_t smb = s2u(gsm);
    uint32_t dstBh[2], dstBl[2], dstAh[2], dstAl[2];
    #pragma unroll
    for (int b = 0; b < 2; b++) {
        dstBh[b] = smb + (uint32_t)((G_SBH + b * G_BBUF + rB * G_BSTR + cB) * 2);
        dstBl[b] = smb + (uint32_t)((G_SBL + b * G_BBUF + rB * G_BSTR + cB) * 2);
        dstAh[b] = smb + (uint32_t)((G_SAH + b * G_ABUF + rA * G_ASTR + cA) * 2);
        dstAl[b] = smb + (uint32_t)((G_SAL + b * G_ABUF + rA * G_ASTR + cA) * 2);
    }

    // ldmatrix source addresses
    const int lm = lane >> 3, lr = lane & 7;
    // B (trans): rows k, cols n
    const int lkrow = (lm & 1) * 8 + lr;
    const int lncol = wc + (lm >> 1) * 8;
    uint32_t sbh_base[2], sbl_base[2];
    // A (non-trans): matrices m0: rows0-7 k0, m1: rows8-15 k0, m2: rows0-7 k8, m3: rows8-15 k8
    const int arow = wm * 16 + (lm & 1) * 8 + lr;
    const int acol = (lane >> 4) * 8;
    uint32_t sah_base[2], sal_base[2];
    #pragma unroll
    for (int b = 0; b < 2; b++) {
        sbh_base[b] = smb + (uint32_t)((G_SBH + b * G_BBUF + lkrow * G_BSTR + lncol) * 2);
        sbl_base[b] = smb + (uint32_t)((G_SBL + b * G_BBUF + lkrow * G_BSTR + lncol) * 2);
        sah_base[b] = smb + (uint32_t)((G_SAH + b * G_ABUF + arow * G_ASTR + acol) * 2);
        sal_base[b] = smb + (uint32_t)((G_SAL + b * G_ABUF + arow * G_ASTR + acol) * 2);
    }

    // prologue: issue tile 0
    {
        const ushort_t* bh = &Bhi[rB * NPIX + bn + cB];
        const ushort_t* bl = &Blo[rB * NPIX + bn + cB];
        CPA16(dstBh[0], bh); CPA16(dstBh[0] + 128, bh + 64);
        CPA16(dstBl[0], bl); CPA16(dstBl[0] + 128, bl + 64);
        CPA16(dstAh[0], &Ahi[(bm + rA) * GK + cA]);
        CPA16(dstAl[0], &Alo[(bm + rA) * GK + cA]);
        CPC();
    }

    #pragma unroll
    for (int ki = 0; ki < 6; ki++) {
        if (ki < 5) {
            const int kn = (ki + 1) * 32;
            const int bf = (ki + 1) & 1;
            const ushort_t* bh = &Bhi[(kn + rB) * NPIX + bn + cB];
            const ushort_t* bl = &Blo[(kn + rB) * NPIX + bn + cB];
            CPA16(dstBh[bf], bh); CPA16(dstBh[bf] + 128, bh + 64);
            CPA16(dstBl[bf], bl); CPA16(dstBl[bf] + 128, bl + 64);
            CPA16(dstAh[bf], &Ahi[(bm + rA) * GK + kn + cA]);
            CPA16(dstAl[bf], &Alo[(bm + rA) * GK + kn + cA]);
            CPC();
            CPW1();
        } else {
            CPW0();
        }
        __syncthreads();

        const int buf = ki & 1;
        #pragma unroll
        for (int hh = 0; hh < 2; hh++) {
            uint32_t ah[4], al[4];
            ldsm4(ah[0], ah[1], ah[2], ah[3], sah_base[buf] + hh * 32);
            ldsm4(al[0], al[1], al[2], al[3], sal_base[buf] + hh * 32);

            const uint32_t hoff = (uint32_t)(hh * 16 * G_BSTR) * 2;
            #pragma unroll
            for (int j = 0; j < 4; j++) {
                uint32_t off = hoff + (uint32_t)(j * 16) * 2;
                uint32_t bh0, bh1, bh2, bh3, bl0, bl1, bl2, bl3;
                ldsm4t(bh0, bh1, bh2, bh3, sbh_base[buf] + off);
                ldsm4t(bl0, bl1, bl2, bl3, sbl_base[buf] + off);
                float* c0 = acc[2 * j];
                float* c1 = acc[2 * j + 1];
                mma_bf16(c0, ah[0], ah[1], ah[2], ah[3], bh0, bh1);
                mma_bf16(c0, al[0], al[1], al[2], al[3], bh0, bh1);
                mma_bf16(c0, ah[0], ah[1], ah[2], ah[3], bl0, bl1);
                mma_bf16(c1, ah[0], ah[1], ah[2], ah[3], bh2, bh3);
                mma_bf16(c1, al[0], al[1], al[2], al[3], bh2, bh3);
                mma_bf16(c1, ah[0], ah[1], ah[2], ah[3], bl2, bl3);
            }
        }
        __syncthreads();
    }

    const float b0 = bias[row0], b1 = bias[row1];
    #pragma unroll
    for (int nf = 0; nf < 8; nf++) {
        int col = bn + wc + nf * 8 + 2 * q;
        *(float2*)&C[row0 * NPIX + col] = make_float2(acc[nf][0] + b0, acc[nf][1] + b0);
        *(float2*)&C[row1 * NPIX + col] = make_float2(acc[nf][2] + b1, acc[nf][3] + b1);
    }
}

// ============================================================================
// mma.sync bf16 flash attention — full K/V resident, ldmatrix fragments
// ============================================================================
#define KSTR 40        // K row stride (halves): 80B, 16B-cluster rotation 5n%8 conflict-free
#define VSTRF 792      // V^T row stride (halves): 1584B, rotation 3n%8 conflict-free
#define NW    14

// SMEM byte offsets
#define A_SKH 0
#define A_SKL (A_SKH + LTOK * KSTR * 2)          // 62720
#define A_SVH (A_SKL + LTOK * KSTR * 2)          // 125440
#define A_SVL (A_SVH + HDIM * VSTRF * 2)         // 163456
#define A_SB  (A_SVL + HDIM * VSTRF * 2)         // 201472
#define A_TOTAL (A_SB + 256)

__global__ __launch_bounds__(448, 1) void attn_mma(
    const float* __restrict__ tab_h, const float* __restrict__ tab_v)
{
    extern __shared__ char asm_[];
    ushort_t* sKhi = (ushort_t*)(asm_ + A_SKH);
    ushort_t* sKlo = (ushort_t*)(asm_ + A_SKL);
    ushort_t* sVhi = (ushort_t*)(asm_ + A_SVH);
    ushort_t* sVlo = (ushort_t*)(asm_ + A_SVL);
    float* sb = (float*)(asm_ + A_SB);

    const int tid = threadIdx.x;
    const int w = blockIdx.x, h = blockIdx.y, br = blockIdx.z;
    const float* __restrict__ qkv = br ? g_qkv_v : g_qkv_h;
    float* __restrict__ outp = br ? g_att_v : g_att_h;
    const float* __restrict__ tab = br ? tab_v : tab_h;

    if (tid < 49) {
        int r1 = tid / 7, r2 = tid % 7, off = r1 - r2 + 6;
        sb[tid] = br ? tab[(6 * 13 + off) * NHEAD + h]
                     : tab[(off * 13 + 6) * NHEAD + h];
    }
    // zero K pad halves 24..31 (read by ldmatrix m3), V pad keys 784..791
    for (int i = tid; i < LTOK * 8; i += 448) {
        int k = i >> 3, d = 24 + (i & 7);
        sKhi[k * KSTR + d] = 0; sKlo[k * KSTR + d] = 0;
    }
    if (tid < HDIM * 8) {
        int d = tid >> 3, k = LTOK + (tid & 7);
        sVhi[d * VSTRF + k] = 0; sVlo[d * VSTRF + k] = 0;
    }
    for (int idx = tid; idx < LTOK * HDIM; idx += 448) {
        int d = idx / LTOK, k = idx - d * LTOK;
        int pix = br ? ((k / 7) * 112 + w * 7 + (k % 7)) : (w * LTOK + k);
        float kv = qkv[(192 + h * HDIM + d) * HWPIX + pix];
        float vv = qkv[(384 + h * HDIM + d) * HWPIX + pix];
        __nv_bfloat16 kh = __float2bfloat16(kv);
        __nv_bfloat16 vh = __float2bfloat16(vv);
        sKhi[k * KSTR + d] = __bfloat16_as_ushort(kh);
        sKlo[k * KSTR + d] = __bfloat16_as_ushort(__float2bfloat16(kv - __bfloat162float(kh)));
        sVhi[d * VSTRF + k] = __bfloat16_as_ushort(vh);
        sVlo[d * VSTRF + k] = __bfloat16_as_ushort(__float2bfloat16(vv - __bfloat162float(vh)));
    }
    __syncthreads();

    const int warp = tid >> 5, lane = tid & 31;
    const int g = lane >> 2, q = lane & 3;
    const int d0 = 2 * q;
    const int lr = lane & 7;

    // ldmatrix lane address components
    // K (B-frag, non-trans): x4 = {k0-7, k8-15, k16-23, k24-31(zeros)}; rows = key n
    const uint32_t kln = (uint32_t)((lr * KSTR + (lane >> 3) * 8) * 2);
    const uint32_t skh_b = s2u(sKhi) + kln;
    const uint32_t skl_b = s2u(sKlo) + kln;
    // V (B-frag, non-trans): rows = dim d, 16B = 8 keys
    const int vko = ((lane >> 3) & 1) * 8;
    const int vdh = ((lane >> 4) & 1) * 8 + lr;
    const uint32_t sv1 = s2u(sVhi) + (uint32_t)((vdh * VSTRF + vko) * 2);           // nd0 hi | nd1 hi
    const uint32_t sv2 = (lane < 16)
        ? s2u(sVhi) + (uint32_t)(((16 + lr) * VSTRF + vko) * 2)                     // nd2 hi
        : s2u(sVlo) + (uint32_t)((lr * VSTRF + vko) * 2);                           // nd0 lo
    const uint32_t sv3 = s2u(sVlo) + (uint32_t)(((8 + ((lane >> 4) & 1) * 8 + lr) * VSTRF + vko) * 2); // nd1 lo | nd2 lo

    for (int mt = warp; mt < 49; mt += NW) {
        const int r0 = mt * 16 + g, r1 = r0 + 8;
        const int pix0 = br ? ((r0 / 7) * 112 + w * 7 + (r0 % 7)) : (w * LTOK + r0);
        const int pix1 = br ? ((r1 / 7) * 112 + w * 7 + (r1 % 7)) : (w * LTOK + r1);
        const int bro0 = (br ? (r0 % 7) : (r0 / 112)) * 7;
        const int bro1 = (br ? (r1 % 7) : (r1 / 112)) * 7;

        uint32_t qh[6], ql[6];
        #pragma unroll
        for (int p = 0; p < 3; p++) {
            int d = d0 + 8 * p;
            float a0v = qkv[(h * HDIM + d)     * HWPIX + pix0] * SCALE_F;
            float a1v = qkv[(h * HDIM + d + 1) * HWPIX + pix0] * SCALE_F;
            float b0v = qkv[(h * HDIM + d)     * HWPIX + pix1] * SCALE_F;
            float b1v = qkv[(h * HDIM + d + 1) * HWPIX + pix1] * SCALE_F;
            uint32_t hA = bfp(a0v, a1v), hB = bfp(b0v, b1v);
            qh[2 * p] = hA; qh[2 * p + 1] = hB;
            ql[2 * p]     = bfp(a0v - bflo(hA), a1v - bfhi(hA));
            ql[2 * p + 1] = bfp(b0v - bflo(hB), b1v - bfhi(hB));
        }

        float o[3][4];
        #pragma unroll
        for (int nd = 0; nd < 3; nd++)
            #pragma unroll
            for (int i = 0; i < 4; i++) o[nd][i] = 0.f;
        float rs0 = 0.f, rs1 = 0.f;

        for (int kt = 0; kt < 14; kt++) {
            float bh0 = 0.f, bh1 = 0.f;
            if (!br) { bh0 = sb[bro0 + (kt >> 1)]; bh1 = sb[bro1 + (kt >> 1)]; }
            const int kbase = kt * 56;

            #pragma unroll
            for (int ks = 0; ks < 4; ks++) {
                const int nt0 = 2 * ks, nt1 = nt0 + 1;
                const bool has1 = (nt1 < 7);
                float sA[4] = {0.f, 0.f, 0.f, 0.f};
                float sB[4] = {0.f, 0.f, 0.f, 0.f};

                {
                    uint32_t ko = (uint32_t)((kbase + nt0 * 8) * KSTR * 2);
                    uint32_t h0, h1, h2, h3, l0, l1, l2, l3;
                    ldsm4(h0, h1, h2, h3, skh_b + ko);
                    ldsm4(l0, l1, l2, l3, skl_b + ko);
                    mma_bf16(sA, qh[0], qh[1], qh[2], qh[3], h0, h1);
                    mma_bf16(sA, ql[0], ql[1], ql[2], ql[3], h0, h1);
                    mma_bf16(sA, qh[0], qh[1], qh[2], qh[3], l0, l1);
                    mma_bf16(sA, qh[4], qh[5], 0u, 0u, h2, h3);
                    mma_bf16(sA, ql[4], ql[5], 0u, 0u, h2, h3);
                    mma_bf16(sA, qh[4], qh[5], 0u, 0u, l2, l3);
                }
                if (has1) {
                    uint32_t ko = (uint32_t)((kbase + nt1 * 8) * KSTR * 2);
                    uint32_t h0, h1, h2, h3, l0, l1, l2, l3;
                    ldsm4(h0, h1, h2, h3, skh_b + ko);
                    ldsm4(l0, l1, l2, l3, skl_b + ko);
                    mma_bf16(sB, qh[0], qh[1], qh[2], qh[3], h0, h1);
                    mma_bf16(sB, ql[0], ql[1], ql[2], ql[3], h0, h1);
                    mma_bf16(sB, qh[0], qh[1], qh[2], qh[3], l0, l1);
                    mma_bf16(sB, qh[4], qh[5], 0u, 0u, h2, h3);
                    mma_bf16(sB, ql[4], ql[5], 0u, 0u, h2, h3);
                    mma_bf16(sB, qh[4], qh[5], 0u, 0u, l2, l3);
                }

                float eA0, eA1, eA2, eA3, eB0 = 0.f, eB1 = 0.f, eB2 = 0.f, eB3 = 0.f;
                if (!br) {
                    eA0 = __expf(sA[0] + bh0); eA1 = __expf(sA[1] + bh0);
                    eA2 = __expf(sA[2] + bh1); eA3 = __expf(sA[3] + bh1);
                    if (has1) {
                        eB0 = __expf(sB[0] + bh0); eB1 = __expf(sB[1] + bh0);
                        eB2 = __expf(sB[2] + bh1); eB3 = __expf(sB[3] + bh1);
                    }
                } else {
                    int i0 = (nt0 + d0) % 7;
                    int i1 = i0 + 1; if (i1 == 7) i1 = 0;
                    int j1 = i1 + 1; if (j1 == 7) j1 = 0;
                    eA0 = __expf(sA[0] + sb[bro0 + i0]); eA1 = __expf(sA[1] + sb[bro0 + i1]);
                    eA2 = __expf(sA[2] + sb[bro1 + i0]); eA3 = __expf(sA[3] + sb[bro1 + i1]);
                    if (has1) {
                        eB0 = __expf(sB[0] + sb[bro0 + i1]); eB1 = __expf(sB[1] + sb[bro0 + j1]);
                        eB2 = __expf(sB[2] + sb[bro1 + i1]); eB3 = __expf(sB[3] + sb[bro1 + j1]);
                    }
                }
                rs0 += eA0 + eA1 + eB0 + eB1;
                rs1 += eA2 + eA3 + eB2 + eB3;

                uint32_t pa0 = bfp(eA0, eA1), pa1 = bfp(eA2, eA3);
                uint32_t pa2 = has1 ? bfp(eB0, eB1) : 0u;
                uint32_t pa3 = has1 ? bfp(eB2, eB3) : 0u;
                uint32_t pl0 = bfp(eA0 - bflo(pa0), eA1 - bfhi(pa0));
                uint32_t pl1 = bfp(eA2 - bflo(pa1), eA3 - bfhi(pa1));
                uint32_t pl2 = has1 ? bfp(eB0 - bflo(pa2), eB1 - bfhi(pa2)) : 0u;
                uint32_t pl3 = has1 ? bfp(eB2 - bflo(pa3), eB3 - bfhi(pa3)) : 0u;

                {
                    uint32_t vo = (uint32_t)((kbase + ks * 16) * 2);
                    uint32_t va0, va1, va2, va3, vb0, vb1, vb2, vb3, vc0, vc1, vc2, vc3;
                    ldsm4(va0, va1, va2, va3, sv1 + vo);   // nd0 hi (va0,va1) | nd1 hi (va2,va3)
                    ldsm4(vb0, vb1, vb2, vb3, sv2 + vo);   // nd2 hi (vb0,vb1) | nd0 lo (vb2,vb3)
                    ldsm4(vc0, vc1, vc2, vc3, sv3 + vo);   // nd1 lo (vc0,vc1) | nd2 lo (vc2,vc3)
                    mma_bf16(o[0], pa0, pa1, pa2, pa3, va0, va1);
                    mma_bf16(o[0], pl0, pl1, pl2, pl3, va0, va1);
                    mma_bf16(o[0], pa0, pa1, pa2, pa3, vb2, vb3);
                    mma_bf16(o[1], pa0, pa1, pa2, pa3, va2, va3);
                    mma_bf16(o[1], pl0, pl1, pl2, pl3, va2, va3);
                    mma_bf16(o[1], pa0, pa1, pa2, pa3, vc0, vc1);
                    mma_bf16(o[2], pa0, pa1, pa2, pa3, vb0, vb1);
                    mma_bf16(o[2], pl0, pl1, pl2, pl3, vb0, vb1);
                    mma_bf16(o[2], pa0, pa1, pa2, pa3, vc2, vc3);
                }
            }
        }

        rs0 += __shfl_xor_sync(0xFFFFFFFFu, rs0, 1);
        rs0 += __shfl_xor_sync(0xFFFFFFFFu, rs0, 2);
        rs1 += __shfl_xor_sync(0xFFFFFFFFu, rs1, 1);
        rs1 += __shfl_xor_sync(0xFFFFFFFFu, rs1, 2);
        float inv0 = 1.f / rs0, inv1 = 1.f / rs1;
        #pragma unroll
        for (int nd = 0; nd < 3; nd++) {
            int d = nd * 8 + d0;
            outp[(h * HDIM + d)     * HWPIX + pix0] = o[nd][0] * inv0;
            outp[(h * HDIM + d + 1) * HWPIX + pix0] = o[nd][1] * inv0;
            outp[(h * HDIM + d)     * HWPIX + pix1] = o[nd][2] * inv1;
            outp[(h * HDIM + d + 1) * HWPIX + pix1] = o[nd][3] * inv1;
        }
    }
}

// ---------------- fused dual LePE -> 0.5*(h+v) -> bf16 hi/lo planes ----------------
__global__ __launch_bounds__(256) void lepe_fused(
    const float* __restrict__ attH, const float* __restrict__ attV,
    const float* __restrict__ wH, const float* __restrict__ bH,
    const float* __restrict__ wV, const float* __restrict__ bV,
    ushort_t* __restrict__ phi, ushort_t* __restrict__ plo)
{
    int t = blockIdx.x * blockDim.x + threadIdx.x;
    if (t >= Cdim * (HWPIX / 4)) return;
    int c = t / (HWPIX / 4);
    int r = t % (HWPIX / 4);
    int y = r / 28, x4 = (r % 28) * 4;
    const float* baseH = attH + c * HWPIX;
    const float* baseV = attV + c * HWPIX;

    float wvh[9], wvv[9];
    #pragma unroll
    for (int i = 0; i < 9; i++) { wvh[i] = wH[c * 9 + i]; wvv[i] = wV[c * 9 + i]; }
    float ah0 = bH[c], ah1 = ah0, ah2 = ah0, ah3 = ah0;
    float av0 = bV[c], av1 = av0, av2 = av0, av3 = av0;

    #pragma unroll
    for (int ky = 0; ky < 3; ky++) {
        int yy = y + ky - 1;
        if (yy < 0 || yy >= 112) continue;
        const float* rpH = baseH + yy * 112 + x4;
        const float* rpV = baseV + yy * 112 + x4;
        float4 mH = *(const float4*)rpH;
        float4 mV = *(const float4*)rpV;
        float lfH = (x4 > 0)   ? rpH[-1] : 0.f;
        float rtH = (x4 < 108) ? rpH[4]  : 0.f;
        float lfV = (x4 > 0)   ? rpV[-1] : 0.f;
        float rtV = (x4 < 108) ? rpV[4]  : 0.f;
        float h0 = wvh[ky*3], h1 = wvh[ky*3+1], h2 = wvh[ky*3+2];
        float v0 = wvv[ky*3], v1 = wvv[ky*3+1], v2 = wvv[ky*3+2];
        ah0 += h0 * lfH  + h1 * mH.x + h2 * mH.y;
        ah1 += h0 * mH.x + h1 * mH.y + h2 * mH.z;
        ah2 += h0 * mH.y + h1 * mH.z + h2 * mH.w;
        ah3 += h0 * mH.z + h1 * mH.w + h2 * rtH;
        av0 += v0 * lfV  + v1 * mV.x + v2 * mV.y;
        av1 += v0 * mV.x + v1 * mV.y + v2 * mV.z;
        av2 += v0 * mV.y + v1 * mV.z + v2 * mV.w;
        av3 += v0 * mV.z + v1 * mV.w + v2 * rtV;
    }

    float4 inH = *(const float4*)(baseH + y * 112 + x4);
    float4 inV = *(const float4*)(baseV + y * 112 + x4);
    const float RS2 = 0.70710678118654752f;
    float oh0 = inH.x + 0.5f * ah0 * (1.f + erff(ah0 * RS2));
    float oh1 = inH.y + 0.5f * ah1 * (1.f + erff(ah1 * RS2));
    float oh2 = inH.z + 0.5f * ah2 * (1.f + erff(ah2 * RS2));
    float oh3 = inH.w + 0.5f * ah3 * (1.f + erff(ah3 * RS2));
    float ov0 = inV.x + 0.5f * av0 * (1.f + erff(av0 * RS2));
    float ov1 = inV.y + 0.5f * av1 * (1.f + erff(av1 * RS2));
    float ov2 = inV.z + 0.5f * av2 * (1.f + erff(av2 * RS2));
    float ov3 = inV.w + 0.5f * av3 * (1.f + erff(av3 * RS2));

    float p0 = 0.5f * (oh0 + ov0);
    float p1 = 0.5f * (oh1 + ov1);
    float p2 = 0.5f * (oh2 + ov2);
    float p3 = 0.5f * (oh3 + ov3);

    uint32_t h0w = bfp(p0, p1), h1w = bfp(p2, p3);
    uint32_t l0w = bfp(p0 - bflo(h0w), p1 - bfhi(h0w));
    uint32_t l1w = bfp(p2 - bflo(h1w), p3 - bfhi(h1w));
    int idx = c * HWPIX + y * 112 + x4;
    *(uint2*)&phi[idx] = make_uint2(h0w, h1w);
    *(uint2*)&plo[idx] = make_uint2(l0w, l1w);
}

// ---------------- launch ----------------
extern "C" void kernel_launch(void* const* d_in, const int* in_sizes, int n_in,
                              void* d_out, int out_size)
{
    const float* x        = (const float*)d_in[0];
    const float* qkv_h_w  = (const float*)d_in[1];
    const float* qkv_h_b  = (const float*)d_in[2];
    const float* qkv_v_w  = (const float*)d_in[3];
    const float* qkv_v_b  = (const float*)d_in[4];
    const float* proj_w   = (const float*)d_in[5];
    const float* proj_b   = (const float*)d_in[6];
    const float* lepe_h_w = (const float*)d_in[7];
    const float* lepe_h_b = (const float*)d_in[8];
    const float* lepe_v_w = (const float*)d_in[9];
    const float* lepe_v_b = (const float*)d_in[10];
    const float* tab_h    = (const float*)d_in[11];
    const float* tab_v    = (const float*)d_in[12];
    float* out = (float*)d_out;

    float *qh, *qv, *ah, *av;
    ushort_t *xhi, *xlo, *phi, *plo, *whh, *whl, *wvh, *wvl, *pwh, *pwl;
    cudaGetSymbolAddress((void**)&qh, g_qkv_h);
    cudaGetSymbolAddress((void**)&qv, g_qkv_v);
    cudaGetSymbolAddress((void**)&ah, g_att_h);
    cudaGetSymbolAddress((void**)&av, g_att_v);
    cudaGetSymbolAddress((void**)&xhi, g_xhi);
    cudaGetSymbolAddress((void**)&xlo, g_xlo);
    cudaGetSymbolAddress((void**)&phi, g_phi);
    cudaGetSymbolAddress((void**)&plo, g_plo);
    cudaGetSymbolAddress((void**)&whh, g_whh);
    cudaGetSymbolAddress((void**)&whl, g_whl);
    cudaGetSymbolAddress((void**)&wvh, g_wvh);
    cudaGetSymbolAddress((void**)&wvl, g_wvl);
    cudaGetSymbolAddress((void**)&pwh, g_pwh);
    cudaGetSymbolAddress((void**)&pwl, g_pwl);

    // split x + all weights
    int nx4 = GK * NPIX / 4;
    split_kernel<<<(nx4 + 255) / 256, 256>>>((const float4*)x, (uint2*)xhi, (uint2*)xlo, nx4);
    int nw4 = M_QKV * GK / 4;
    int np4 = M_PROJ * GK / 4;
    int ntotw = nw4 * 2 + np4;
    split_weights<<<(ntotw + 255) / 256, 256>>>(
        (const float4*)qkv_h_w, (uint2*)whh, (uint2*)whl, nw4,
        (const float4*)qkv_v_w, (uint2*)wvh, (uint2*)wvl, nw4,
        (const float4*)proj_w,  (uint2*)pwh, (uint2*)pwl, np4);

    // QKV GEMMs (tensor core, staged A + B, cp.async DB)
    cudaFuncSetAttribute(gemm_mma,
                         cudaFuncAttributeMaxDynamicSharedMemorySize, G_TOTAL_BYTES);
    dim3 gq(NPIX / 128, M_QKV / 64);
    gemm_mma<<<gq, 256, G_TOTAL_BYTES>>>(whh, whl, xhi, xlo, qkv_h_b, qh);
    gemm_mma<<<gq, 256, G_TOTAL_BYTES>>>(wvh, wvl, xhi, xlo, qkv_v_b, qv);

    // attention (full K/V resident, ldmatrix frags)
    cudaFuncSetAttribute(attn_mma,
                         cudaFuncAttributeMaxDynamicSharedMemorySize, A_TOTAL);
    dim3 ga(16, NHEAD, 2);
    attn_mma<<<ga, 448, A_TOTAL>>>(tab_h, tab_v);

    // fused dual LePE + average + split
    int nthr = Cdim * (HWPIX / 4);
    lepe_fused<<<(nthr + 255) / 256, 256>>>(ah, av, lepe_h_w, lepe_h_b,
                                            lepe_v_w, lepe_v_b, phi, plo);

    // projection GEMM
    dim3 gp(NPIX / 128, M_PROJ / 64);
    gemm_mma<<<gp, 256, G_TOTAL_BYTES>>>(pwh, pwl, phi, plo, proj_b, out);
}